// round 1
// baseline (speedup 1.0000x reference)
#include <cuda_runtime.h>
#include <math.h>

#define Bb  2
#define Ss  2048
#define Dd  2048
#define HDv 128
#define NH  16
#define NKV 8
#define MS  (Bb*Ss)          // 4096 tokens

// ---------------- scratch (device globals; no allocation allowed) ----------
__device__ float g_q_raw[MS*NH*HDv];    // [4096][2048]
__device__ float g_k_raw[MS*NKV*HDv];   // [4096][1024]
__device__ float g_v_raw[MS*NKV*HDv];
__device__ float g_qt[Bb*NH*Ss*HDv];    // [B,H,S,hd]
__device__ float g_kt[Bb*NKV*Ss*HDv];   // [B,KV,S,hd]
__device__ float g_vt[Bb*NKV*Ss*HDv];
__device__ float g_attn[MS*NH*HDv];     // [4096][2048]

// ---------------- SGEMM: C[M,N] = A[M,K] @ B[K,N], all row-major ----------
#define GBM 128
#define GBN 128
#define GBK 16
__global__ void __launch_bounds__(256, 2)
sgemm_kernel(const float* __restrict__ A, const float* __restrict__ Bm,
             float* __restrict__ C, int M, int N, int K)
{
    __shared__ float As[GBK][GBM];  // stored transposed
    __shared__ float Bs[GBK][GBN];
    const int tid = threadIdx.x;
    const int tc = tid % 16;        // col group
    const int tr = tid / 16;        // row group
    const int aRow = tid / 4;            // 0..63
    const int aCol = (tid % 4) * 4;      // 0..12
    const int bRow = tid / 32;           // 0..7
    const int bCol = (tid % 32) * 4;     // 0..124

    const float* Ap = A + (size_t)blockIdx.y * GBM * K;
    const float* Bp = Bm + blockIdx.x * GBN;

    float acc[8][8];
    #pragma unroll
    for (int i = 0; i < 8; i++)
        #pragma unroll
        for (int j = 0; j < 8; j++) acc[i][j] = 0.f;

    for (int k0 = 0; k0 < K; k0 += GBK) {
        #pragma unroll
        for (int h = 0; h < 2; h++) {
            int r = aRow + h * 64;
            float4 v = *(const float4*)(Ap + (size_t)r * K + k0 + aCol);
            As[aCol + 0][r] = v.x; As[aCol + 1][r] = v.y;
            As[aCol + 2][r] = v.z; As[aCol + 3][r] = v.w;
        }
        #pragma unroll
        for (int h = 0; h < 2; h++) {
            int r = bRow + h * 8;
            *(float4*)(&Bs[r][bCol]) = *(const float4*)(Bp + (size_t)(k0 + r) * N + bCol);
        }
        __syncthreads();
        #pragma unroll
        for (int kk = 0; kk < GBK; kk++) {
            float a[8], b[8];
            #pragma unroll
            for (int i = 0; i < 8; i += 4) *(float4*)(a + i) = *(float4*)(&As[kk][tr * 8 + i]);
            #pragma unroll
            for (int j = 0; j < 8; j += 4) *(float4*)(b + j) = *(float4*)(&Bs[kk][tc * 8 + j]);
            #pragma unroll
            for (int i = 0; i < 8; i++)
                #pragma unroll
                for (int j = 0; j < 8; j++) acc[i][j] += a[i] * b[j];
        }
        __syncthreads();
    }
    float* Cp = C + (size_t)(blockIdx.y * GBM + tr * 8) * N + blockIdx.x * GBN + tc * 8;
    #pragma unroll
    for (int i = 0; i < 8; i++)
        #pragma unroll
        for (int j = 0; j < 8; j += 4)
            *(float4*)(Cp + (size_t)i * N + j) =
                make_float4(acc[i][j], acc[i][j+1], acc[i][j+2], acc[i][j+3]);
}

// ------------- per-(token, head): RMSNorm + mRoPE + transpose -------------
__global__ void normrope_kernel(const float* __restrict__ cosp, const float* __restrict__ sinp,
                                const float* __restrict__ qw,   const float* __restrict__ kw)
{
    const int tok = blockIdx.x;       // b*S + s
    const int hh  = blockIdx.y;       // 0..15 q, 16..23 k, 24..31 v
    const int d   = threadIdx.x;      // 0..127
    const int b = tok / Ss, s_ = tok % Ss;

    if (hh >= NH + NKV) {             // V: plain transpose
        int h = hh - NH - NKV;
        g_vt[((size_t)(b * NKV + h) * Ss + s_) * HDv + d] =
            g_v_raw[(size_t)tok * (NKV * HDv) + h * HDv + d];
        return;
    }
    __shared__ float xs[HDv];
    __shared__ float red[4];
    const bool isq = hh < NH;
    float x = isq ? g_q_raw[(size_t)tok * (NH * HDv) + hh * HDv + d]
                  : g_k_raw[(size_t)tok * (NKV * HDv) + (hh - NH) * HDv + d];
    float sq = x * x;
    #pragma unroll
    for (int off = 16; off > 0; off >>= 1) sq += __shfl_xor_sync(0xffffffffu, sq, off);
    if ((d & 31) == 0) red[d >> 5] = sq;
    __syncthreads();
    float var = (red[0] + red[1] + red[2] + red[3]) * (1.0f / HDv);
    float inv = rsqrtf(var + 1e-6f);
    float xn  = (isq ? qw[d] : kw[d]) * (x * inv);
    xs[d] = xn;
    __syncthreads();
    // mRoPE sections [16,24,24]*2 -> modality per dim
    int dd  = d & 63;
    int mod = dd < 16 ? 0 : (dd < 40 ? 1 : 2);
    size_t ci = (((size_t)mod * Bb + b) * Ss + s_) * HDv + d;
    float c = cosp[ci], sn = sinp[ci];
    float rh = (d < 64) ? -xs[d + 64] : xs[d - 64];
    float y = xn * c + rh * sn;
    if (isq) g_qt[((size_t)(b * NH  + hh)        * Ss + s_) * HDv + d] = y;
    else     g_kt[((size_t)(b * NKV + (hh - NH)) * Ss + s_) * HDv + d] = y;
}

// ------------- flash-style causal attention (fp32, online softmax) --------
#define FM  128     // query rows per block
#define FN  64      // key cols per tile
#define KP  129     // padded row stride (bank spread)
#define PSP 68      // P tile row stride

__global__ void __launch_bounds__(256, 1) flash_kernel()
{
    extern __shared__ float sm[];
    float* Qs = sm;                   // FM x KP
    float* Ks = Qs + FM * KP;         // FN x KP
    float* Vs = Ks + FN * KP;         // FN x KP
    float* Ps = Vs + FN * KP;         // FM x PSP

    const int tid = threadIdx.x;
    const int tx = tid & 15, ty = tid >> 4;
    const int qb = blockIdx.x, h = blockIdx.y, b = blockIdx.z;
    const int kv = h >> 1;            // GQA: groups = 2

    const float* qbase = g_qt + ((size_t)(b * NH  + h ) * Ss + qb * FM) * HDv;
    const float* kbase = g_kt + ((size_t)(b * NKV + kv) * Ss) * HDv;
    const float* vbase = g_vt + ((size_t)(b * NKV + kv) * Ss) * HDv;

    // load Q tile (once)
    #pragma unroll
    for (int it = 0; it < (FM * HDv / 4) / 256; it++) {
        int idx = tid + it * 256;
        int row = idx >> 5, d4 = (idx & 31) * 4;
        float4 v = *(const float4*)(qbase + row * HDv + d4);
        float* p = Qs + row * KP + d4;
        p[0] = v.x; p[1] = v.y; p[2] = v.z; p[3] = v.w;
    }
    float o[8][8], m[8], l[8];
    #pragma unroll
    for (int r = 0; r < 8; r++) {
        m[r] = -1e30f; l[r] = 0.f;
        #pragma unroll
        for (int dd = 0; dd < 8; dd++) o[r][dd] = 0.f;
    }
    __syncthreads();

    const int nkb = 2 * qb + 2;       // causal: keys up to end of q block
    for (int kb = 0; kb < nkb; kb++) {
        #pragma unroll
        for (int it = 0; it < (FN * HDv / 4) / 256; it++) {
            int idx = tid + it * 256;
            int row = idx >> 5, d4 = (idx & 31) * 4;
            float4 kq = *(const float4*)(kbase + (size_t)(kb * FN + row) * HDv + d4);
            float* pk = Ks + row * KP + d4;
            pk[0] = kq.x; pk[1] = kq.y; pk[2] = kq.z; pk[3] = kq.w;
            float4 vq = *(const float4*)(vbase + (size_t)(kb * FN + row) * HDv + d4);
            float* pv = Vs + row * KP + d4;
            pv[0] = vq.x; pv[1] = vq.y; pv[2] = vq.z; pv[3] = vq.w;
        }
        __syncthreads();

        float s[8][4];
        #pragma unroll
        for (int r = 0; r < 8; r++)
            #pragma unroll
            for (int c = 0; c < 4; c++) s[r][c] = 0.f;
        for (int kd = 0; kd < HDv; kd++) {
            float qr[8], kc[4];
            #pragma unroll
            for (int r = 0; r < 8; r++) qr[r] = Qs[(ty * 8 + r) * KP + kd];
            #pragma unroll
            for (int c = 0; c < 4; c++) kc[c] = Ks[(tx * 4 + c) * KP + kd];
            #pragma unroll
            for (int r = 0; r < 8; r++)
                #pragma unroll
                for (int c = 0; c < 4; c++) s[r][c] += qr[r] * kc[c];
        }
        const float scale = 0.08838834764831845f;   // 128^-0.5
        #pragma unroll
        for (int r = 0; r < 8; r++) {
            int qi = qb * FM + ty * 8 + r;
            float rowmax = -1e30f;
            #pragma unroll
            for (int c = 0; c < 4; c++) {
                int kj = kb * FN + tx * 4 + c;
                float sv = (kj <= qi) ? s[r][c] * scale : -1e30f;
                s[r][c] = sv;
                rowmax = fmaxf(rowmax, sv);
            }
            #pragma unroll
            for (int off = 8; off > 0; off >>= 1)
                rowmax = fmaxf(rowmax, __shfl_xor_sync(0xffffffffu, rowmax, off));
            float mnew  = fmaxf(m[r], rowmax);
            float alpha = __expf(m[r] - mnew);
            float rs = 0.f;
            #pragma unroll
            for (int c = 0; c < 4; c++) {
                float p = __expf(s[r][c] - mnew);
                Ps[(ty * 8 + r) * PSP + tx * 4 + c] = p;
                rs += p;
            }
            #pragma unroll
            for (int off = 8; off > 0; off >>= 1)
                rs += __shfl_xor_sync(0xffffffffu, rs, off);
            l[r] = l[r] * alpha + rs;
            m[r] = mnew;
            #pragma unroll
            for (int dd = 0; dd < 8; dd++) o[r][dd] *= alpha;
        }
        __syncthreads();
        for (int j = 0; j < FN; j++) {
            float pv[8], vv[8];
            #pragma unroll
            for (int r = 0; r < 8; r++)  pv[r]  = Ps[(ty * 8 + r) * PSP + j];
            #pragma unroll
            for (int dd = 0; dd < 8; dd++) vv[dd] = Vs[j * KP + dd * 16 + tx];
            #pragma unroll
            for (int r = 0; r < 8; r++)
                #pragma unroll
                for (int dd = 0; dd < 8; dd++) o[r][dd] += pv[r] * vv[dd];
        }
        __syncthreads();
    }
    // epilogue: normalize + write [b, s, h*128 + d]
    #pragma unroll
    for (int r = 0; r < 8; r++) {
        float inv = 1.f / l[r];
        int srow = qb * FM + ty * 8 + r;
        float* outp = g_attn + (size_t)(b * Ss + srow) * (NH * HDv) + h * HDv;
        #pragma unroll
        for (int dd = 0; dd < 8; dd++) outp[dd * 16 + tx] = o[r][dd] * inv;
    }
}

// --------------------------------- launch ---------------------------------
extern "C" void kernel_launch(void* const* d_in, const int* in_sizes, int n_in,
                              void* d_out, int out_size)
{
    const float* hs   = (const float*)d_in[0];
    const float* cosp = (const float*)d_in[1];
    const float* sinp = (const float*)d_in[2];
    // d_in[3] = attention_mask: exactly causal -1e9; implemented analytically
    const float* Wq = (const float*)d_in[4];
    const float* Wk = (const float*)d_in[5];
    const float* Wv = (const float*)d_in[6];
    const float* Wo = (const float*)d_in[7];
    const float* qw = (const float*)d_in[8];
    const float* kw = (const float*)d_in[9];
    float* out = (float*)d_out;

    void *pq, *pk, *pv, *pattn;
    cudaGetSymbolAddress(&pq, g_q_raw);
    cudaGetSymbolAddress(&pk, g_k_raw);
    cudaGetSymbolAddress(&pv, g_v_raw);
    cudaGetSymbolAddress(&pattn, g_attn);

    dim3 blk(256);
    // QKV projections
    sgemm_kernel<<<dim3(2048 / GBN, 4096 / GBM), blk>>>(hs, Wq, (float*)pq, 4096, 2048, 2048);
    sgemm_kernel<<<dim3(1024 / GBN, 4096 / GBM), blk>>>(hs, Wk, (float*)pk, 4096, 1024, 2048);
    sgemm_kernel<<<dim3(1024 / GBN, 4096 / GBM), blk>>>(hs, Wv, (float*)pv, 4096, 1024, 2048);
    // norm + rope + transpose
    normrope_kernel<<<dim3(MS, NH + 2 * NKV), 128>>>(cosp, sinp, qw, kw);
    // flash attention
    const int smem = (FM * KP + 2 * FN * KP + FM * PSP) * 4;
    cudaFuncSetAttribute(flash_kernel, cudaFuncAttributeMaxDynamicSharedMemorySize, smem);
    flash_kernel<<<dim3(Ss / FM, NH, Bb), 256, smem>>>();
    // output projection
    sgemm_kernel<<<dim3(2048 / GBN, 4096 / GBM), blk>>>((const float*)pattn, Wo, out, 4096, 2048, 2048);
}

// round 3
// speedup vs baseline: 1.7180x; 1.7180x over previous
#include <cuda_runtime.h>
#include <math.h>
#include <stdint.h>

#define Bb  2
#define Ss  2048
#define Dd  2048
#define HDv 128
#define NH  16
#define NKV 8
#define MS  (Bb*Ss)          // 4096 tokens

// ---------------- scratch (device globals; no allocation allowed) ----------
__device__ float g_q_raw[MS*NH*HDv];
__device__ float g_k_raw[MS*NKV*HDv];
__device__ float g_v_raw[MS*NKV*HDv];
__device__ float g_qt[Bb*NH*Ss*HDv];
__device__ float g_kt[Bb*NKV*Ss*HDv];
__device__ float g_vt[Bb*NKV*Ss*HDv];
__device__ float g_attn[MS*NH*HDv];
__device__ float g_wqt[Dd*Dd];            // Wq^T  [N, K]
__device__ float g_wkt[(NKV*HDv)*Dd];
__device__ float g_wvt[(NKV*HDv)*Dd];
__device__ float g_wot[Dd*Dd];

// ------------------------------ PTX helpers -------------------------------
__device__ __forceinline__ uint32_t smem_u32(const void* p) {
    uint32_t a;
    asm("{ .reg .u64 t; cvta.to.shared.u64 t, %1; cvt.u32.u64 %0, t; }" : "=r"(a) : "l"(p));
    return a;
}
__device__ __forceinline__ void cp_async16(uint32_t saddr, const void* g) {
    asm volatile("cp.async.cg.shared.global [%0], [%1], 16;" :: "r"(saddr), "l"(g));
}
__device__ __forceinline__ void cp_commit() { asm volatile("cp.async.commit_group;" ::: "memory"); }
template <int N> __device__ __forceinline__ void cp_wait() {
    asm volatile("cp.async.wait_group %0;" :: "n"(N) : "memory");
}
__device__ __forceinline__ void ldsm4(uint32_t* r, uint32_t addr) {
    asm volatile("ldmatrix.sync.aligned.m8n8.x4.shared.b16 {%0,%1,%2,%3}, [%4];"
                 : "=r"(r[0]), "=r"(r[1]), "=r"(r[2]), "=r"(r[3]) : "r"(addr));
}
__device__ __forceinline__ uint32_t f2tf(uint32_t x) {
    uint32_t y;
    asm("cvt.rna.tf32.f32 %0, %1;" : "=r"(y) : "f"(__uint_as_float(x)));
    return y;
}
__device__ __forceinline__ void mma1688(float* d, const uint32_t* a, uint32_t b0, uint32_t b1) {
    asm volatile(
        "mma.sync.aligned.m16n8k8.row.col.f32.tf32.tf32.f32 "
        "{%0,%1,%2,%3}, {%4,%5,%6,%7}, {%8,%9}, {%0,%1,%2,%3};"
        : "+f"(d[0]), "+f"(d[1]), "+f"(d[2]), "+f"(d[3])
        : "r"(a[0]), "r"(a[1]), "r"(a[2]), "r"(a[3]), "r"(b0), "r"(b1));
}

// -------------------- weight transpose: Wt[n,k] = W[k,n] -------------------
__global__ void transpose_kernel(const float* __restrict__ W, float* __restrict__ Wt,
                                 int K, int N)
{
    __shared__ float t[32][33];
    const int bx = blockIdx.x * 32;   // k block
    const int by = blockIdx.y * 32;   // n block
    const int tx = threadIdx.x, ty = threadIdx.y;
    #pragma unroll
    for (int i = 0; i < 32; i += 8)
        t[ty + i][tx] = W[(size_t)(bx + ty + i) * N + by + tx];
    __syncthreads();
    #pragma unroll
    for (int i = 0; i < 32; i += 8)
        Wt[(size_t)(by + ty + i) * K + bx + tx] = t[tx][ty + i];
}

// --------- tf32 mma.sync GEMM: C[M,N] = A[M,K] @ Bt[N,K]^T ----------------
// CTA tile 128x128x32, 3-stage cp.async pipeline, 8 warps of 64x32.
#define BM 128
#define BN 128
#define BK 32
#define NSTG 3
#define STG_FLOATS (2 * BM * BK)          // A tile + B tile = 8192 floats
#define GEMM_SMEM (NSTG * STG_FLOATS * 4) // 98304 B

__global__ void __launch_bounds__(256)
mma_gemm_kernel(const float* __restrict__ A, const float* __restrict__ Bt,
                float* __restrict__ C, int M, int N, int K)
{
    extern __shared__ float sm[];
    const int tid = threadIdx.x;
    const int lane = tid & 31, w = tid >> 5;
    const int wm = (w & 1) * 64;          // warp m offset in tile
    const int wn = (w >> 1) * 32;         // warp n offset in tile
    const int m0 = blockIdx.y * BM, n0 = blockIdx.x * BN;
    const float* Ap = A  + (size_t)m0 * K;
    const float* Bp = Bt + (size_t)n0 * K;
    const uint32_t sbase = smem_u32(sm);
    const int NCH = K / BK;

    // ldmatrix lane geometry
    const int a_mat  = lane >> 3;
    const int a_rrow = (lane & 7) + ((a_mat & 1) << 3);   // 0..15 within m16 tile
    const int a_crel = a_mat >> 1;                        // 16B chunk within kstep
    const int b_rrow = lane & 7;                          // 0..7 within n8 tile
    const int b_mat  = lane >> 3;                         // k chunk within pair

    auto load_stage = [&](int s, int kt) {
        uint32_t aB = sbase + s * (STG_FLOATS * 4);
        uint32_t bB = aB + BM * BK * 4;
        int k0 = kt * BK;
        #pragma unroll
        for (int i = 0; i < 4; i++) {
            int idx = tid + i * 256;
            int row = idx >> 3, c = idx & 7;
            int phys = c ^ (row & 7);
            cp_async16(aB + row * 128 + phys * 16, Ap + (size_t)row * K + k0 + c * 4);
            cp_async16(bB + row * 128 + phys * 16, Bp + (size_t)row * K + k0 + c * 4);
        }
        cp_commit();
    };

    #pragma unroll
    for (int s = 0; s < NSTG; s++) load_stage(s, s);

    float d[4][4][4];
    #pragma unroll
    for (int i = 0; i < 4; i++)
        #pragma unroll
        for (int j = 0; j < 4; j++)
            #pragma unroll
            for (int q = 0; q < 4; q++) d[i][j][q] = 0.f;

    for (int it = 0; it < NCH; it++) {
        cp_wait<NSTG - 1>();
        __syncthreads();
        uint32_t aB = sbase + (it % NSTG) * (STG_FLOATS * 4);
        uint32_t bB = aB + BM * BK * 4;

        #pragma unroll
        for (int kp = 0; kp < 2; kp++) {      // k-step pairs
            uint32_t bfr[4][4];
            #pragma unroll
            for (int tn = 0; tn < 4; tn++) {
                int row = wn + tn * 8 + b_rrow;
                int chunk = kp * 4 + b_mat;
                int phys = chunk ^ (row & 7);
                ldsm4(bfr[tn], bB + row * 128 + phys * 16);
                #pragma unroll
                for (int q = 0; q < 4; q++) bfr[tn][q] = f2tf(bfr[tn][q]);
            }
            #pragma unroll
            for (int half = 0; half < 2; half++) {
                int ks = kp * 2 + half;
                uint32_t afr[4][4];
                #pragma unroll
                for (int tm = 0; tm < 4; tm++) {
                    int row = wm + tm * 16 + a_rrow;
                    int chunk = ks * 2 + a_crel;
                    int phys = chunk ^ (row & 7);
                    ldsm4(afr[tm], aB + row * 128 + phys * 16);
                    #pragma unroll
                    for (int q = 0; q < 4; q++) afr[tm][q] = f2tf(afr[tm][q]);
                }
                #pragma unroll
                for (int tm = 0; tm < 4; tm++)
                    #pragma unroll
                    for (int tn = 0; tn < 4; tn++)
                        mma1688(d[tm][tn], afr[tm], bfr[tn][half * 2], bfr[tn][half * 2 + 1]);
            }
        }
        __syncthreads();
        if (it + NSTG < NCH) load_stage(it % NSTG, it + NSTG);
    }

    // epilogue
    const int crow = lane >> 2, ccol = (lane & 3) * 2;
    #pragma unroll
    for (int tm = 0; tm < 4; tm++)
        #pragma unroll
        for (int tn = 0; tn < 4; tn++) {
            float* Cp = C + (size_t)(m0 + wm + tm * 16 + crow) * N + n0 + wn + tn * 8 + ccol;
            *(float2*)Cp            = make_float2(d[tm][tn][0], d[tm][tn][1]);
            *(float2*)(Cp + 8 * (size_t)N) = make_float2(d[tm][tn][2], d[tm][tn][3]);
        }
}

// ------------- per-(token, head): RMSNorm + mRoPE + transpose -------------
__global__ void normrope_kernel(const float* __restrict__ cosp, const float* __restrict__ sinp,
                                const float* __restrict__ qw,   const float* __restrict__ kw)
{
    const int tok = blockIdx.x;
    const int hh  = blockIdx.y;
    const int d   = threadIdx.x;
    const int b = tok / Ss, s_ = tok % Ss;

    if (hh >= NH + NKV) {
        int h = hh - NH - NKV;
        g_vt[((size_t)(b * NKV + h) * Ss + s_) * HDv + d] =
            g_v_raw[(size_t)tok * (NKV * HDv) + h * HDv + d];
        return;
    }
    __shared__ float xs[HDv];
    __shared__ float red[4];
    const bool isq = hh < NH;
    float x = isq ? g_q_raw[(size_t)tok * (NH * HDv) + hh * HDv + d]
                  : g_k_raw[(size_t)tok * (NKV * HDv) + (hh - NH) * HDv + d];
    float sq = x * x;
    #pragma unroll
    for (int off = 16; off > 0; off >>= 1) sq += __shfl_xor_sync(0xffffffffu, sq, off);
    if ((d & 31) == 0) red[d >> 5] = sq;
    __syncthreads();
    float var = (red[0] + red[1] + red[2] + red[3]) * (1.0f / HDv);
    float inv = rsqrtf(var + 1e-6f);
    float xn  = (isq ? qw[d] : kw[d]) * (x * inv);
    xs[d] = xn;
    __syncthreads();
    int dd  = d & 63;
    int mod = dd < 16 ? 0 : (dd < 40 ? 1 : 2);
    size_t ci = (((size_t)mod * Bb + b) * Ss + s_) * HDv + d;
    float c = cosp[ci], sn = sinp[ci];
    float rh = (d < 64) ? -xs[d + 64] : xs[d - 64];
    float y = xn * c + rh * sn;
    if (isq) g_qt[((size_t)(b * NH  + hh)        * Ss + s_) * HDv + d] = y;
    else     g_kt[((size_t)(b * NKV + (hh - NH)) * Ss + s_) * HDv + d] = y;
}

// ------------- flash-style causal attention (fp32, online softmax) --------
#define FM  128
#define FN  64
#define KP  129
#define PSP 68

__global__ void __launch_bounds__(256, 1) flash_kernel()
{
    extern __shared__ float sm[];
    float* Qs = sm;
    float* Ks = Qs + FM * KP;
    float* Vs = Ks + FN * KP;
    float* Ps = Vs + FN * KP;

    const int tid = threadIdx.x;
    const int tx = tid & 15, ty = tid >> 4;
    const int qb = blockIdx.x, h = blockIdx.y, b = blockIdx.z;
    const int kv = h >> 1;

    const float* qbase = g_qt + ((size_t)(b * NH  + h ) * Ss + qb * FM) * HDv;
    const float* kbase = g_kt + ((size_t)(b * NKV + kv) * Ss) * HDv;
    const float* vbase = g_vt + ((size_t)(b * NKV + kv) * Ss) * HDv;

    #pragma unroll
    for (int it = 0; it < (FM * HDv / 4) / 256; it++) {
        int idx = tid + it * 256;
        int row = idx >> 5, d4 = (idx & 31) * 4;
        float4 v = *(const float4*)(qbase + row * HDv + d4);
        float* p = Qs + row * KP + d4;
        p[0] = v.x; p[1] = v.y; p[2] = v.z; p[3] = v.w;
    }
    float o[8][8], m[8], l[8];
    #pragma unroll
    for (int r = 0; r < 8; r++) {
        m[r] = -1e30f; l[r] = 0.f;
        #pragma unroll
        for (int dd = 0; dd < 8; dd++) o[r][dd] = 0.f;
    }
    __syncthreads();

    const int nkb = 2 * qb + 2;
    for (int kb = 0; kb < nkb; kb++) {
        #pragma unroll
        for (int it = 0; it < (FN * HDv / 4) / 256; it++) {
            int idx = tid + it * 256;
            int row = idx >> 5, d4 = (idx & 31) * 4;
            float4 kq = *(const float4*)(kbase + (size_t)(kb * FN + row) * HDv + d4);
            float* pk = Ks + row * KP + d4;
            pk[0] = kq.x; pk[1] = kq.y; pk[2] = kq.z; pk[3] = kq.w;
            float4 vq = *(const float4*)(vbase + (size_t)(kb * FN + row) * HDv + d4);
            float* pv = Vs + row * KP + d4;
            pv[0] = vq.x; pv[1] = vq.y; pv[2] = vq.z; pv[3] = vq.w;
        }
        __syncthreads();

        float s[8][4];
        #pragma unroll
        for (int r = 0; r < 8; r++)
            #pragma unroll
            for (int c = 0; c < 4; c++) s[r][c] = 0.f;
        for (int kd = 0; kd < HDv; kd++) {
            float qr[8], kc[4];
            #pragma unroll
            for (int r = 0; r < 8; r++) qr[r] = Qs[(ty * 8 + r) * KP + kd];
            #pragma unroll
            for (int c = 0; c < 4; c++) kc[c] = Ks[(tx * 4 + c) * KP + kd];
            #pragma unroll
            for (int r = 0; r < 8; r++)
                #pragma unroll
                for (int c = 0; c < 4; c++) s[r][c] += qr[r] * kc[c];
        }
        const float scale = 0.08838834764831845f;
        #pragma unroll
        for (int r = 0; r < 8; r++) {
            int qi = qb * FM + ty * 8 + r;
            float rowmax = -1e30f;
            #pragma unroll
            for (int c = 0; c < 4; c++) {
                int kj = kb * FN + tx * 4 + c;
                float sv = (kj <= qi) ? s[r][c] * scale : -1e30f;
                s[r][c] = sv;
                rowmax = fmaxf(rowmax, sv);
            }
            #pragma unroll
            for (int off = 8; off > 0; off >>= 1)
                rowmax = fmaxf(rowmax, __shfl_xor_sync(0xffffffffu, rowmax, off));
            float mnew  = fmaxf(m[r], rowmax);
            float alpha = __expf(m[r] - mnew);
            float rs = 0.f;
            #pragma unroll
            for (int c = 0; c < 4; c++) {
                float p = __expf(s[r][c] - mnew);
                Ps[(ty * 8 + r) * PSP + tx * 4 + c] = p;
                rs += p;
            }
            #pragma unroll
            for (int off = 8; off > 0; off >>= 1)
                rs += __shfl_xor_sync(0xffffffffu, rs, off);
            l[r] = l[r] * alpha + rs;
            m[r] = mnew;
            #pragma unroll
            for (int dd = 0; dd < 8; dd++) o[r][dd] *= alpha;
        }
        __syncthreads();
        for (int j = 0; j < FN; j++) {
            float pv[8], vv[8];
            #pragma unroll
            for (int r = 0; r < 8; r++)  pv[r]  = Ps[(ty * 8 + r) * PSP + j];
            #pragma unroll
            for (int dd = 0; dd < 8; dd++) vv[dd] = Vs[j * KP + dd * 16 + tx];
            #pragma unroll
            for (int r = 0; r < 8; r++)
                #pragma unroll
                for (int dd = 0; dd < 8; dd++) o[r][dd] += pv[r] * vv[dd];
        }
        __syncthreads();
    }
    #pragma unroll
    for (int r = 0; r < 8; r++) {
        float inv = 1.f / l[r];
        int srow = qb * FM + ty * 8 + r;
        float* outp = g_attn + (size_t)(b * Ss + srow) * (NH * HDv) + h * HDv;
        #pragma unroll
        for (int dd = 0; dd < 8; dd++) outp[dd * 16 + tx] = o[r][dd] * inv;
    }
}

// --------------------------------- launch ---------------------------------
extern "C" void kernel_launch(void* const* d_in, const int* in_sizes, int n_in,
                              void* d_out, int out_size)
{
    const float* hs   = (const float*)d_in[0];
    const float* cosp = (const float*)d_in[1];
    const float* sinp = (const float*)d_in[2];
    // d_in[3] = attention_mask: exactly causal -1e9; implemented analytically
    const float* Wq = (const float*)d_in[4];
    const float* Wk = (const float*)d_in[5];
    const float* Wv = (const float*)d_in[6];
    const float* Wo = (const float*)d_in[7];
    const float* qw = (const float*)d_in[8];
    const float* kw = (const float*)d_in[9];
    float* out = (float*)d_out;

    void *pq, *pk, *pv, *pattn, *pwqt, *pwkt, *pwvt, *pwot;
    cudaGetSymbolAddress(&pq, g_q_raw);
    cudaGetSymbolAddress(&pk, g_k_raw);
    cudaGetSymbolAddress(&pv, g_v_raw);
    cudaGetSymbolAddress(&pattn, g_attn);
    cudaGetSymbolAddress(&pwqt, g_wqt);
    cudaGetSymbolAddress(&pwkt, g_wkt);
    cudaGetSymbolAddress(&pwvt, g_wvt);
    cudaGetSymbolAddress(&pwot, g_wot);

    dim3 tb(32, 8);
    transpose_kernel<<<dim3(Dd / 32, Dd / 32), tb>>>(Wq, (float*)pwqt, Dd, Dd);
    transpose_kernel<<<dim3(Dd / 32, (NKV * HDv) / 32), tb>>>(Wk, (float*)pwkt, Dd, NKV * HDv);
    transpose_kernel<<<dim3(Dd / 32, (NKV * HDv) / 32), tb>>>(Wv, (float*)pwvt, Dd, NKV * HDv);
    transpose_kernel<<<dim3(Dd / 32, Dd / 32), tb>>>(Wo, (float*)pwot, Dd, Dd);

    cudaFuncSetAttribute(mma_gemm_kernel,
                         cudaFuncAttributeMaxDynamicSharedMemorySize, GEMM_SMEM);
    mma_gemm_kernel<<<dim3(16, 32), 256, GEMM_SMEM>>>(hs, (const float*)pwqt, (float*)pq, 4096, 2048, 2048);
    mma_gemm_kernel<<<dim3(8, 32), 256, GEMM_SMEM>>>(hs, (const float*)pwkt, (float*)pk, 4096, 1024, 2048);
    mma_gemm_kernel<<<dim3(8, 32), 256, GEMM_SMEM>>>(hs, (const float*)pwvt, (float*)pv, 4096, 1024, 2048);

    normrope_kernel<<<dim3(MS, NH + 2 * NKV), 128>>>(cosp, sinp, qw, kw);

    const int smem = (FM * KP + 2 * FN * KP + FM * PSP) * 4;
    cudaFuncSetAttribute(flash_kernel, cudaFuncAttributeMaxDynamicSharedMemorySize, smem);
    flash_kernel<<<dim3(Ss / FM, NH, Bb), 256, smem>>>();

    mma_gemm_kernel<<<dim3(16, 32), 256, GEMM_SMEM>>>((const float*)pattn, (const float*)pwot, out, 4096, 2048, 2048);
}

// round 4
// speedup vs baseline: 3.3057x; 1.9242x over previous
#include <cuda_runtime.h>
#include <math.h>
#include <stdint.h>

#define Bb  2
#define Ss  2048
#define Dd  2048
#define HDv 128
#define NH  16
#define NKV 8
#define MS  (Bb*Ss)          // 4096 tokens

// ---------------- scratch (device globals; no allocation allowed) ----------
__device__ float g_q_raw[MS*NH*HDv];
__device__ float g_k_raw[MS*NKV*HDv];
__device__ float g_v_raw[MS*NKV*HDv];
__device__ float g_qt[Bb*NH*Ss*HDv];
__device__ float g_kt[Bb*NKV*Ss*HDv];
__device__ float g_vt[Bb*NKV*Ss*HDv];    // [b,kv,s,d]
__device__ float g_vtd[Bb*NKV*HDv*Ss];   // [b,kv,d,s]  (for PV B-operand)
__device__ float g_attn[MS*NH*HDv];
__device__ float g_wqt[Dd*Dd];           // Wq^T  [N, K]
__device__ float g_wkt[(NKV*HDv)*Dd];
__device__ float g_wvt[(NKV*HDv)*Dd];
__device__ float g_wot[Dd*Dd];

// ------------------------------ PTX helpers -------------------------------
__device__ __forceinline__ uint32_t smem_u32(const void* p) {
    uint32_t a;
    asm("{ .reg .u64 t; cvta.to.shared.u64 t, %1; cvt.u32.u64 %0, t; }" : "=r"(a) : "l"(p));
    return a;
}
__device__ __forceinline__ void cp_async16(uint32_t saddr, const void* g) {
    asm volatile("cp.async.cg.shared.global [%0], [%1], 16;" :: "r"(saddr), "l"(g));
}
__device__ __forceinline__ void cp_commit() { asm volatile("cp.async.commit_group;" ::: "memory"); }
template <int N> __device__ __forceinline__ void cp_wait() {
    asm volatile("cp.async.wait_group %0;" :: "n"(N) : "memory");
}
__device__ __forceinline__ void ldsm4(uint32_t* r, uint32_t addr) {
    asm volatile("ldmatrix.sync.aligned.m8n8.x4.shared.b16 {%0,%1,%2,%3}, [%4];"
                 : "=r"(r[0]), "=r"(r[1]), "=r"(r[2]), "=r"(r[3]) : "r"(addr));
}
__device__ __forceinline__ uint32_t f2tf(uint32_t x) {
    uint32_t y;
    asm("cvt.rna.tf32.f32 %0, %1;" : "=r"(y) : "f"(__uint_as_float(x)));
    return y;
}
__device__ __forceinline__ void sts8(uint32_t addr, float a, float b) {
    asm volatile("st.shared.v2.f32 [%0], {%1, %2};" :: "r"(addr), "f"(a), "f"(b) : "memory");
}
__device__ __forceinline__ void mma1688(float* d, const uint32_t* a, uint32_t b0, uint32_t b1) {
    asm volatile(
        "mma.sync.aligned.m16n8k8.row.col.f32.tf32.tf32.f32 "
        "{%0,%1,%2,%3}, {%4,%5,%6,%7}, {%8,%9}, {%0,%1,%2,%3};"
        : "+f"(d[0]), "+f"(d[1]), "+f"(d[2]), "+f"(d[3])
        : "r"(a[0]), "r"(a[1]), "r"(a[2]), "r"(a[3]), "r"(b0), "r"(b1));
}

// -------------------- weight transpose: Wt[n,k] = W[k,n] -------------------
__global__ void transpose_kernel(const float* __restrict__ W, float* __restrict__ Wt,
                                 int K, int N)
{
    __shared__ float t[32][33];
    const int bx = blockIdx.x * 32;
    const int by = blockIdx.y * 32;
    const int tx = threadIdx.x, ty = threadIdx.y;
    #pragma unroll
    for (int i = 0; i < 32; i += 8)
        t[ty + i][tx] = W[(size_t)(bx + ty + i) * N + by + tx];
    __syncthreads();
    #pragma unroll
    for (int i = 0; i < 32; i += 8)
        Wt[(size_t)(by + ty + i) * K + bx + tx] = t[tx][ty + i];
}

// ------------- V transpose per head: [s, d] -> [d, s] ----------------------
__global__ void vtrans_kernel()
{
    __shared__ float t[32][33];
    const int bh = blockIdx.z;
    const int s0 = blockIdx.x * 32, d0 = blockIdx.y * 32;
    const int tx = threadIdx.x, ty = threadIdx.y;
    const float* in = g_vt + (size_t)bh * Ss * HDv;
    float* outp = g_vtd + (size_t)bh * HDv * Ss;
    #pragma unroll
    for (int i = 0; i < 32; i += 8)
        t[ty + i][tx] = in[(size_t)(s0 + ty + i) * HDv + d0 + tx];
    __syncthreads();
    #pragma unroll
    for (int i = 0; i < 32; i += 8)
        outp[(size_t)(d0 + ty + i) * Ss + s0 + tx] = t[tx][ty + i];
}

// --------- tf32 mma.sync GEMM: C[M,N] = A[M,K] @ Bt[N,K]^T ----------------
#define BM 128
#define BN 128
#define BK 32
#define NSTG 3
#define STG_FLOATS (2 * BM * BK)
#define GEMM_SMEM (NSTG * STG_FLOATS * 4)

__global__ void __launch_bounds__(256)
mma_gemm_kernel(const float* __restrict__ A, const float* __restrict__ Bt,
                float* __restrict__ C, int M, int N, int K)
{
    extern __shared__ float sm[];
    const int tid = threadIdx.x;
    const int lane = tid & 31, w = tid >> 5;
    const int wm = (w & 1) * 64;
    const int wn = (w >> 1) * 32;
    const int m0 = blockIdx.y * BM, n0 = blockIdx.x * BN;
    const float* Ap = A  + (size_t)m0 * K;
    const float* Bp = Bt + (size_t)n0 * K;
    const uint32_t sbase = smem_u32(sm);
    const int NCH = K / BK;

    const int a_mat  = lane >> 3;
    const int a_rrow = (lane & 7) + ((a_mat & 1) << 3);
    const int a_crel = a_mat >> 1;
    const int b_rrow = lane & 7;
    const int b_mat  = lane >> 3;

    auto load_stage = [&](int s, int kt) {
        uint32_t aB = sbase + s * (STG_FLOATS * 4);
        uint32_t bB = aB + BM * BK * 4;
        int k0 = kt * BK;
        #pragma unroll
        for (int i = 0; i < 4; i++) {
            int idx = tid + i * 256;
            int row = idx >> 3, c = idx & 7;
            int phys = c ^ (row & 7);
            cp_async16(aB + row * 128 + phys * 16, Ap + (size_t)row * K + k0 + c * 4);
            cp_async16(bB + row * 128 + phys * 16, Bp + (size_t)row * K + k0 + c * 4);
        }
        cp_commit();
    };

    #pragma unroll
    for (int s = 0; s < NSTG; s++) load_stage(s, s);

    float d[4][4][4];
    #pragma unroll
    for (int i = 0; i < 4; i++)
        #pragma unroll
        for (int j = 0; j < 4; j++)
            #pragma unroll
            for (int q = 0; q < 4; q++) d[i][j][q] = 0.f;

    for (int it = 0; it < NCH; it++) {
        cp_wait<NSTG - 1>();
        __syncthreads();
        uint32_t aB = sbase + (it % NSTG) * (STG_FLOATS * 4);
        uint32_t bB = aB + BM * BK * 4;

        #pragma unroll
        for (int kp = 0; kp < 2; kp++) {
            uint32_t bfr[4][4];
            #pragma unroll
            for (int tn = 0; tn < 4; tn++) {
                int row = wn + tn * 8 + b_rrow;
                int chunk = kp * 4 + b_mat;
                int phys = chunk ^ (row & 7);
                ldsm4(bfr[tn], bB + row * 128 + phys * 16);
                #pragma unroll
                for (int q = 0; q < 4; q++) bfr[tn][q] = f2tf(bfr[tn][q]);
            }
            #pragma unroll
            for (int half = 0; half < 2; half++) {
                int ks = kp * 2 + half;
                uint32_t afr[4][4];
                #pragma unroll
                for (int tm = 0; tm < 4; tm++) {
                    int row = wm + tm * 16 + a_rrow;
                    int chunk = ks * 2 + a_crel;
                    int phys = chunk ^ (row & 7);
                    ldsm4(afr[tm], aB + row * 128 + phys * 16);
                    #pragma unroll
                    for (int q = 0; q < 4; q++) afr[tm][q] = f2tf(afr[tm][q]);
                }
                #pragma unroll
                for (int tm = 0; tm < 4; tm++)
                    #pragma unroll
                    for (int tn = 0; tn < 4; tn++)
                        mma1688(d[tm][tn], afr[tm], bfr[tn][half * 2], bfr[tn][half * 2 + 1]);
            }
        }
        __syncthreads();
        if (it + NSTG < NCH) load_stage(it % NSTG, it + NSTG);
    }

    const int crow = lane >> 2, ccol = (lane & 3) * 2;
    #pragma unroll
    for (int tm = 0; tm < 4; tm++)
        #pragma unroll
        for (int tn = 0; tn < 4; tn++) {
            float* Cp = C + (size_t)(m0 + wm + tm * 16 + crow) * N + n0 + wn + tn * 8 + ccol;
            *(float2*)Cp                   = make_float2(d[tm][tn][0], d[tm][tn][1]);
            *(float2*)(Cp + 8 * (size_t)N) = make_float2(d[tm][tn][2], d[tm][tn][3]);
        }
}

// ------------- per-(token, head): RMSNorm + mRoPE + transpose -------------
__global__ void normrope_kernel(const float* __restrict__ cosp, const float* __restrict__ sinp,
                                const float* __restrict__ qw,   const float* __restrict__ kw)
{
    const int tok = blockIdx.x;
    const int hh  = blockIdx.y;
    const int d   = threadIdx.x;
    const int b = tok / Ss, s_ = tok % Ss;

    if (hh >= NH + NKV) {
        int h = hh - NH - NKV;
        g_vt[((size_t)(b * NKV + h) * Ss + s_) * HDv + d] =
            g_v_raw[(size_t)tok * (NKV * HDv) + h * HDv + d];
        return;
    }
    __shared__ float xs[HDv];
    __shared__ float red[4];
    const bool isq = hh < NH;
    float x = isq ? g_q_raw[(size_t)tok * (NH * HDv) + hh * HDv + d]
                  : g_k_raw[(size_t)tok * (NKV * HDv) + (hh - NH) * HDv + d];
    float sq = x * x;
    #pragma unroll
    for (int off = 16; off > 0; off >>= 1) sq += __shfl_xor_sync(0xffffffffu, sq, off);
    if ((d & 31) == 0) red[d >> 5] = sq;
    __syncthreads();
    float var = (red[0] + red[1] + red[2] + red[3]) * (1.0f / HDv);
    float inv = rsqrtf(var + 1e-6f);
    float xn  = (isq ? qw[d] : kw[d]) * (x * inv);
    xs[d] = xn;
    __syncthreads();
    int dd  = d & 63;
    int mod = dd < 16 ? 0 : (dd < 40 ? 1 : 2);
    size_t ci = (((size_t)mod * Bb + b) * Ss + s_) * HDv + d;
    float c = cosp[ci], sn = sinp[ci];
    float rh = (d < 64) ? -xs[d + 64] : xs[d - 64];
    float y = xn * c + rh * sn;
    if (isq) g_qt[((size_t)(b * NH  + hh)        * Ss + s_) * HDv + d] = y;
    else     g_kt[((size_t)(b * NKV + (hh - NH)) * Ss + s_) * HDv + d] = y;
}

// ------------- flash attention with tf32 mma.sync --------------------------
#define FM  128          // q rows per CTA
#define FNN 64           // keys per iteration
#define QS_OFF 0         // 128 x 512B swizzled        (64 KB)
#define KS_OFF 65536     // 2 x (64 x 512B)            (64 KB)
#define KS_SZ  32768
#define VS_OFF 131072    // 2 x (128 x 256B)  [d, key] (64 KB)
#define VS_SZ  32768
#define PS_OFF 196608    // 128 x 256B swizzled        (32 KB)
#define FSMEM  229376

__global__ void __launch_bounds__(256, 1) flashmma_kernel()
{
    extern __shared__ float sm[];
    const uint32_t sb = smem_u32(sm);
    const int tid = threadIdx.x, lane = tid & 31, w = tid >> 5;
    const int qb = blockIdx.x, h = blockIdx.y, b = blockIdx.z;
    const int kv = h >> 1;

    const float* qbase = g_qt  + ((size_t)(b * NH  + h ) * Ss + qb * FM) * HDv;
    const float* kbase = g_kt  + ((size_t)(b * NKV + kv) * Ss) * HDv;
    const float* vbase = g_vtd + ((size_t)(b * NKV + kv) * HDv) * Ss;

    // Q tile: 128 rows x 32 chunks(16B), swizzled
    #pragma unroll
    for (int i = 0; i < 16; i++) {
        int idx = tid + i * 256;
        int row = idx >> 5, c = idx & 31;
        cp_async16(sb + QS_OFF + row * 512 + ((c ^ (row & 7)) * 16),
                   qbase + (size_t)row * HDv + c * 4);
    }
    cp_commit();

    auto loadKV = [&](int s, int kb) {
        uint32_t kB = sb + KS_OFF + s * KS_SZ;
        uint32_t vB = sb + VS_OFF + s * VS_SZ;
        #pragma unroll
        for (int i = 0; i < 8; i++) {
            int idx = tid + i * 256;
            int row = idx >> 5, c = idx & 31;           // 64 rows x 32 chunks
            cp_async16(kB + row * 512 + ((c ^ (row & 7)) * 16),
                       kbase + (size_t)(kb * FNN + row) * HDv + c * 4);
        }
        #pragma unroll
        for (int i = 0; i < 8; i++) {
            int idx = tid + i * 256;
            int row = idx >> 4, c = idx & 15;           // 128 rows x 16 chunks
            cp_async16(vB + row * 256 + ((c ^ (row & 7)) * 16),
                       vbase + (size_t)row * Ss + kb * FNN + c * 4);
        }
        cp_commit();
    };
    loadKV(0, 0);

    // fragment geometry
    const int a_mat  = lane >> 3;
    const int a_rrow = (lane & 7) + ((a_mat & 1) << 3);
    const int a_crel = a_mat >> 1;
    const int b_rrow = lane & 7;
    const int b_mat  = lane >> 3;
    const int q0 = lane >> 2;
    const int c0 = (lane & 3) * 2;

    float o[16][4];
    #pragma unroll
    for (int nt = 0; nt < 16; nt++)
        #pragma unroll
        for (int q = 0; q < 4; q++) o[nt][q] = 0.f;
    float mrow[2] = {-1e30f, -1e30f}, lrow[2] = {0.f, 0.f};

    const int nkb = 2 * qb + 2;
    const int arow = w * 16 + a_rrow;

    for (int kb = 0; kb < nkb; kb++) {
        int s = kb & 1;
        cp_wait<0>();
        __syncthreads();
        if (kb + 1 < nkb) loadKV(s ^ 1, kb + 1);

        uint32_t kB = sb + KS_OFF + s * KS_SZ;
        uint32_t vB = sb + VS_OFF + s * VS_SZ;

        // ---- S = Q K^T : this warp's 16 q-rows x 64 keys ----
        float sfr[8][4];
        #pragma unroll
        for (int nt = 0; nt < 8; nt++)
            #pragma unroll
            for (int q = 0; q < 4; q++) sfr[nt][q] = 0.f;

        #pragma unroll
        for (int kp = 0; kp < 8; kp++) {
            uint32_t bfr[8][4];
            #pragma unroll
            for (int nt = 0; nt < 8; nt++) {
                int row = nt * 8 + b_rrow;
                int chunk = kp * 4 + b_mat;
                ldsm4(bfr[nt], kB + row * 512 + ((chunk ^ (row & 7)) * 16));
                #pragma unroll
                for (int q = 0; q < 4; q++) bfr[nt][q] = f2tf(bfr[nt][q]);
            }
            #pragma unroll
            for (int half = 0; half < 2; half++) {
                int ks = kp * 2 + half;
                uint32_t afr[4];
                int chunk = ks * 2 + a_crel;
                ldsm4(afr, sb + QS_OFF + arow * 512 + ((chunk ^ (arow & 7)) * 16));
                #pragma unroll
                for (int q = 0; q < 4; q++) afr[q] = f2tf(afr[q]);
                #pragma unroll
                for (int nt = 0; nt < 8; nt++)
                    mma1688(sfr[nt], afr, bfr[nt][half * 2], bfr[nt][half * 2 + 1]);
            }
        }

        // ---- online softmax on fragments ----
        const float scale = 0.08838834764831845f;
        const bool need_mask = (kb >= 2 * qb);
        #pragma unroll
        for (int r = 0; r < 2; r++) {
            int qi = qb * FM + w * 16 + q0 + r * 8;
            float vals[16];
            float mx = -1e30f;
            #pragma unroll
            for (int nt = 0; nt < 8; nt++)
                #pragma unroll
                for (int q = 0; q < 2; q++) {
                    float v = sfr[nt][r * 2 + q] * scale;
                    if (need_mask) {
                        int kj = kb * FNN + nt * 8 + c0 + q;
                        if (kj > qi) v = -1e30f;
                    }
                    vals[nt * 2 + q] = v;
                    mx = fmaxf(mx, v);
                }
            mx = fmaxf(mx, __shfl_xor_sync(0xffffffffu, mx, 1));
            mx = fmaxf(mx, __shfl_xor_sync(0xffffffffu, mx, 2));
            float mnew  = fmaxf(mrow[r], mx);
            float alpha = __expf(mrow[r] - mnew);
            float rs = 0.f;
            int prow = w * 16 + q0 + r * 8;
            #pragma unroll
            for (int nt = 0; nt < 8; nt++) {
                float p0 = __expf(vals[nt * 2]     - mnew);
                float p1 = __expf(vals[nt * 2 + 1] - mnew);
                rs += p0 + p1;
                int col = nt * 8 + c0;
                int chunk = col >> 2, within = col & 3;
                sts8(sb + PS_OFF + prow * 256 + ((chunk ^ (prow & 7)) * 16) + within * 4, p0, p1);
            }
            rs += __shfl_xor_sync(0xffffffffu, rs, 1);
            rs += __shfl_xor_sync(0xffffffffu, rs, 2);
            lrow[r] = lrow[r] * alpha + rs;
            mrow[r] = mnew;
            #pragma unroll
            for (int nt = 0; nt < 16; nt++) {
                o[nt][r * 2]     *= alpha;
                o[nt][r * 2 + 1] *= alpha;
            }
        }
        __syncwarp();

        // ---- load P A-fragments (warp-local rows) ----
        uint32_t pa[8][4];
        #pragma unroll
        for (int ks = 0; ks < 8; ks++) {
            int chunk = ks * 2 + a_crel;
            ldsm4(pa[ks], sb + PS_OFF + arow * 256 + ((chunk ^ (arow & 7)) * 16));
            #pragma unroll
            for (int q = 0; q < 4; q++) pa[ks][q] = f2tf(pa[ks][q]);
        }

        // ---- O += P V ----
        #pragma unroll
        for (int nt = 0; nt < 16; nt++) {
            #pragma unroll
            for (int kp = 0; kp < 4; kp++) {
                uint32_t bfr[4];
                int row = nt * 8 + b_rrow;
                int chunk = kp * 4 + b_mat;
                ldsm4(bfr, vB + row * 256 + ((chunk ^ (row & 7)) * 16));
                #pragma unroll
                for (int q = 0; q < 4; q++) bfr[q] = f2tf(bfr[q]);
                mma1688(o[nt], pa[kp * 2],     bfr[0], bfr[1]);
                mma1688(o[nt], pa[kp * 2 + 1], bfr[2], bfr[3]);
            }
        }
    }

    // epilogue
    #pragma unroll
    for (int r = 0; r < 2; r++) {
        float inv = 1.f / lrow[r];
        int row = qb * FM + w * 16 + q0 + r * 8;
        float* outp = g_attn + ((size_t)(b * Ss + row) * (NH * HDv)) + h * HDv;
        #pragma unroll
        for (int nt = 0; nt < 16; nt++)
            *(float2*)(outp + nt * 8 + c0) =
                make_float2(o[nt][r * 2] * inv, o[nt][r * 2 + 1] * inv);
    }
}

// --------------------------------- launch ---------------------------------
extern "C" void kernel_launch(void* const* d_in, const int* in_sizes, int n_in,
                              void* d_out, int out_size)
{
    const float* hs   = (const float*)d_in[0];
    const float* cosp = (const float*)d_in[1];
    const float* sinp = (const float*)d_in[2];
    // d_in[3] = attention_mask: exactly causal -1e9; implemented analytically
    const float* Wq = (const float*)d_in[4];
    const float* Wk = (const float*)d_in[5];
    const float* Wv = (const float*)d_in[6];
    const float* Wo = (const float*)d_in[7];
    const float* qw = (const float*)d_in[8];
    const float* kw = (const float*)d_in[9];
    float* out = (float*)d_out;

    void *pq, *pk, *pv, *pattn, *pwqt, *pwkt, *pwvt, *pwot;
    cudaGetSymbolAddress(&pq, g_q_raw);
    cudaGetSymbolAddress(&pk, g_k_raw);
    cudaGetSymbolAddress(&pv, g_v_raw);
    cudaGetSymbolAddress(&pattn, g_attn);
    cudaGetSymbolAddress(&pwqt, g_wqt);
    cudaGetSymbolAddress(&pwkt, g_wkt);
    cudaGetSymbolAddress(&pwvt, g_wvt);
    cudaGetSymbolAddress(&pwot, g_wot);

    dim3 tb(32, 8);
    transpose_kernel<<<dim3(Dd / 32, Dd / 32), tb>>>(Wq, (float*)pwqt, Dd, Dd);
    transpose_kernel<<<dim3(Dd / 32, (NKV * HDv) / 32), tb>>>(Wk, (float*)pwkt, Dd, NKV * HDv);
    transpose_kernel<<<dim3(Dd / 32, (NKV * HDv) / 32), tb>>>(Wv, (float*)pwvt, Dd, NKV * HDv);
    transpose_kernel<<<dim3(Dd / 32, Dd / 32), tb>>>(Wo, (float*)pwot, Dd, Dd);

    cudaFuncSetAttribute(mma_gemm_kernel,
                         cudaFuncAttributeMaxDynamicSharedMemorySize, GEMM_SMEM);
    mma_gemm_kernel<<<dim3(16, 32), 256, GEMM_SMEM>>>(hs, (const float*)pwqt, (float*)pq, 4096, 2048, 2048);
    mma_gemm_kernel<<<dim3(8, 32), 256, GEMM_SMEM>>>(hs, (const float*)pwkt, (float*)pk, 4096, 1024, 2048);
    mma_gemm_kernel<<<dim3(8, 32), 256, GEMM_SMEM>>>(hs, (const float*)pwvt, (float*)pv, 4096, 1024, 2048);

    normrope_kernel<<<dim3(MS, NH + 2 * NKV), 128>>>(cosp, sinp, qw, kw);
    vtrans_kernel<<<dim3(Ss / 32, HDv / 32, Bb * NKV), tb>>>();

    cudaFuncSetAttribute(flashmma_kernel,
                         cudaFuncAttributeMaxDynamicSharedMemorySize, FSMEM);
    flashmma_kernel<<<dim3(Ss / FM, NH, Bb), 256, FSMEM>>>();

    mma_gemm_kernel<<<dim3(16, 32), 256, GEMM_SMEM>>>((const float*)pattn, (const float*)pwot, out, 4096, 2048, 2048);
}

// round 5
// speedup vs baseline: 3.9631x; 1.1989x over previous
#include <cuda_runtime.h>
#include <math.h>
#include <stdint.h>

#define Bb  2
#define Ss  2048
#define Dd  2048
#define HDv 128
#define NH  16
#define NKV 8
#define MS  (Bb*Ss)          // 4096 tokens
#define NQKV (NH*HDv + 2*NKV*HDv)   // 4096

// ---------------- scratch (device globals; no allocation allowed) ----------
__device__ float g_hs_tf[MS*Dd];          // tf32-rounded hidden states
__device__ float g_qkv[MS*NQKV];          // fused QKV output [tok, 4096]
__device__ float g_qt[Bb*NH*Ss*HDv];      // tf32-rounded
__device__ float g_kt[Bb*NKV*Ss*HDv];     // tf32-rounded
__device__ float g_vt[Bb*NKV*Ss*HDv];     // [b,kv,s,d] raw
__device__ float g_vtd[Bb*NKV*HDv*Ss];    // [b,kv,d,s] tf32-rounded
__device__ float g_attn[MS*NH*HDv];       // tf32-rounded
__device__ float g_wqkvt[NQKV*Dd];        // packed [Wq^T ; Wk^T ; Wv^T], tf32-rounded
__device__ float g_wot[Dd*Dd];            // Wo^T, tf32-rounded

// ------------------------------ PTX helpers -------------------------------
__device__ __forceinline__ uint32_t smem_u32(const void* p) {
    uint32_t a;
    asm("{ .reg .u64 t; cvta.to.shared.u64 t, %1; cvt.u32.u64 %0, t; }" : "=r"(a) : "l"(p));
    return a;
}
__device__ __forceinline__ void cp_async16(uint32_t saddr, const void* g) {
    asm volatile("cp.async.cg.shared.global [%0], [%1], 16;" :: "r"(saddr), "l"(g));
}
__device__ __forceinline__ void cp_commit() { asm volatile("cp.async.commit_group;" ::: "memory"); }
template <int N> __device__ __forceinline__ void cp_wait() {
    asm volatile("cp.async.wait_group %0;" :: "n"(N) : "memory");
}
__device__ __forceinline__ void ldsm4(uint32_t* r, uint32_t addr) {
    asm volatile("ldmatrix.sync.aligned.m8n8.x4.shared.b16 {%0,%1,%2,%3}, [%4];"
                 : "=r"(r[0]), "=r"(r[1]), "=r"(r[2]), "=r"(r[3]) : "r"(addr));
}
__device__ __forceinline__ float f2tf_f(float x) {
    float y;
    asm("cvt.rna.tf32.f32 %0, %1;" : "=f"(y) : "f"(x));
    return y;
}
__device__ __forceinline__ uint32_t f2tf(uint32_t x) {
    uint32_t y;
    asm("cvt.rna.tf32.f32 %0, %1;" : "=r"(y) : "f"(__uint_as_float(x)));
    return y;
}
__device__ __forceinline__ void sts8(uint32_t addr, float a, float b) {
    asm volatile("st.shared.v2.f32 [%0], {%1, %2};" :: "r"(addr), "f"(a), "f"(b) : "memory");
}
__device__ __forceinline__ void mma1688(float* d, const uint32_t* a, uint32_t b0, uint32_t b1) {
    asm volatile(
        "mma.sync.aligned.m16n8k8.row.col.f32.tf32.tf32.f32 "
        "{%0,%1,%2,%3}, {%4,%5,%6,%7}, {%8,%9}, {%0,%1,%2,%3};"
        : "+f"(d[0]), "+f"(d[1]), "+f"(d[2]), "+f"(d[3])
        : "r"(a[0]), "r"(a[1]), "r"(a[2]), "r"(a[3]), "r"(b0), "r"(b1));
}

// ---------- elementwise tf32 rounding pass (for activations) ---------------
__global__ void cvt_kernel(const float* __restrict__ in, float* __restrict__ out, int n4)
{
    int i = blockIdx.x * blockDim.x + threadIdx.x;
    if (i >= n4) return;
    float4 v = ((const float4*)in)[i];
    v.x = f2tf_f(v.x); v.y = f2tf_f(v.y); v.z = f2tf_f(v.z); v.w = f2tf_f(v.w);
    ((float4*)out)[i] = v;
}

// ----------- weight transpose + tf32 round: Wt[n,k] = tf32(W[k,n]) ---------
__global__ void transpose_kernel(const float* __restrict__ W, float* __restrict__ Wt,
                                 int K, int N)
{
    __shared__ float t[32][33];
    const int bx = blockIdx.x * 32;
    const int by = blockIdx.y * 32;
    const int tx = threadIdx.x, ty = threadIdx.y;
    #pragma unroll
    for (int i = 0; i < 32; i += 8)
        t[ty + i][tx] = W[(size_t)(bx + ty + i) * N + by + tx];
    __syncthreads();
    #pragma unroll
    for (int i = 0; i < 32; i += 8)
        Wt[(size_t)(by + ty + i) * K + bx + tx] = f2tf_f(t[tx][ty + i]);
}

// ------------- V transpose per head: [s, d] -> [d, s], tf32 round ----------
__global__ void vtrans_kernel()
{
    __shared__ float t[32][33];
    const int bh = blockIdx.z;
    const int s0 = blockIdx.x * 32, d0 = blockIdx.y * 32;
    const int tx = threadIdx.x, ty = threadIdx.y;
    const float* in = g_vt + (size_t)bh * Ss * HDv;
    float* outp = g_vtd + (size_t)bh * HDv * Ss;
    #pragma unroll
    for (int i = 0; i < 32; i += 8)
        t[ty + i][tx] = in[(size_t)(s0 + ty + i) * HDv + d0 + tx];
    __syncthreads();
    #pragma unroll
    for (int i = 0; i < 32; i += 8)
        outp[(size_t)(d0 + ty + i) * Ss + s0 + tx] = f2tf_f(t[tx][ty + i]);
}

// --------- tf32 mma.sync GEMM: C[M,N] = A[M,K] @ Bt[N,K]^T ----------------
// Operands already tf32-rounded: NO cvt in mainloop.
#define BM 128
#define BN 128
#define BK 32
#define NSTG 3
#define STG_FLOATS (2 * BM * BK)
#define GEMM_SMEM (NSTG * STG_FLOATS * 4)

__global__ void __launch_bounds__(256)
mma_gemm_kernel(const float* __restrict__ A, const float* __restrict__ Bt,
                float* __restrict__ C, int M, int N, int K)
{
    extern __shared__ float sm[];
    const int tid = threadIdx.x;
    const int lane = tid & 31, w = tid >> 5;
    const int wm = (w & 1) * 64;
    const int wn = (w >> 1) * 32;
    const int m0 = blockIdx.y * BM, n0 = blockIdx.x * BN;
    const float* Ap = A  + (size_t)m0 * K;
    const float* Bp = Bt + (size_t)n0 * K;
    const uint32_t sbase = smem_u32(sm);
    const int NCH = K / BK;

    const int a_mat  = lane >> 3;
    const int a_rrow = (lane & 7) + ((a_mat & 1) << 3);
    const int a_crel = a_mat >> 1;
    const int b_rrow = lane & 7;
    const int b_mat  = lane >> 3;

    auto load_stage = [&](int s, int kt) {
        uint32_t aB = sbase + s * (STG_FLOATS * 4);
        uint32_t bB = aB + BM * BK * 4;
        int k0 = kt * BK;
        #pragma unroll
        for (int i = 0; i < 4; i++) {
            int idx = tid + i * 256;
            int row = idx >> 3, c = idx & 7;
            int phys = c ^ (row & 7);
            cp_async16(aB + row * 128 + phys * 16, Ap + (size_t)row * K + k0 + c * 4);
            cp_async16(bB + row * 128 + phys * 16, Bp + (size_t)row * K + k0 + c * 4);
        }
        cp_commit();
    };

    #pragma unroll
    for (int s = 0; s < NSTG; s++) load_stage(s, s);

    float d[4][4][4];
    #pragma unroll
    for (int i = 0; i < 4; i++)
        #pragma unroll
        for (int j = 0; j < 4; j++)
            #pragma unroll
            for (int q = 0; q < 4; q++) d[i][j][q] = 0.f;

    for (int it = 0; it < NCH; it++) {
        cp_wait<NSTG - 1>();
        __syncthreads();
        uint32_t aB = sbase + (it % NSTG) * (STG_FLOATS * 4);
        uint32_t bB = aB + BM * BK * 4;

        #pragma unroll
        for (int kp = 0; kp < 2; kp++) {
            uint32_t bfr[4][4];
            #pragma unroll
            for (int tn = 0; tn < 4; tn++) {
                int row = wn + tn * 8 + b_rrow;
                int chunk = kp * 4 + b_mat;
                int phys = chunk ^ (row & 7);
                ldsm4(bfr[tn], bB + row * 128 + phys * 16);
            }
            #pragma unroll
            for (int half = 0; half < 2; half++) {
                int ks = kp * 2 + half;
                uint32_t afr[4][4];
                #pragma unroll
                for (int tm = 0; tm < 4; tm++) {
                    int row = wm + tm * 16 + a_rrow;
                    int chunk = ks * 2 + a_crel;
                    int phys = chunk ^ (row & 7);
                    ldsm4(afr[tm], aB + row * 128 + phys * 16);
                }
                #pragma unroll
                for (int tm = 0; tm < 4; tm++)
                    #pragma unroll
                    for (int tn = 0; tn < 4; tn++)
                        mma1688(d[tm][tn], afr[tm], bfr[tn][half * 2], bfr[tn][half * 2 + 1]);
            }
        }
        __syncthreads();
        if (it + NSTG < NCH) load_stage(it % NSTG, it + NSTG);
    }

    const int crow = lane >> 2, ccol = (lane & 3) * 2;
    #pragma unroll
    for (int tm = 0; tm < 4; tm++)
        #pragma unroll
        for (int tn = 0; tn < 4; tn++) {
            float* Cp = C + (size_t)(m0 + wm + tm * 16 + crow) * N + n0 + wn + tn * 8 + ccol;
            *(float2*)Cp                   = make_float2(d[tm][tn][0], d[tm][tn][1]);
            *(float2*)(Cp + 8 * (size_t)N) = make_float2(d[tm][tn][2], d[tm][tn][3]);
        }
}

// ------------- per-(token, head): RMSNorm + mRoPE + transpose -------------
// reads from fused g_qkv [tok, 4096]: Q at col h*128, K at 2048+, V at 3072+
__global__ void normrope_kernel(const float* __restrict__ cosp, const float* __restrict__ sinp,
                                const float* __restrict__ qw,   const float* __restrict__ kw)
{
    const int tok = blockIdx.x;
    const int hh  = blockIdx.y;
    const int d   = threadIdx.x;
    const int b = tok / Ss, s_ = tok % Ss;
    const float* row = g_qkv + (size_t)tok * NQKV;

    if (hh >= NH + NKV) {
        int h = hh - NH - NKV;
        g_vt[((size_t)(b * NKV + h) * Ss + s_) * HDv + d] =
            row[3072 + h * HDv + d];
        return;
    }
    __shared__ float xs[HDv];
    __shared__ float red[4];
    const bool isq = hh < NH;
    float x = isq ? row[hh * HDv + d] : row[2048 + (hh - NH) * HDv + d];
    float sq = x * x;
    #pragma unroll
    for (int off = 16; off > 0; off >>= 1) sq += __shfl_xor_sync(0xffffffffu, sq, off);
    if ((d & 31) == 0) red[d >> 5] = sq;
    __syncthreads();
    float var = (red[0] + red[1] + red[2] + red[3]) * (1.0f / HDv);
    float inv = rsqrtf(var + 1e-6f);
    float xn  = (isq ? qw[d] : kw[d]) * (x * inv);
    xs[d] = xn;
    __syncthreads();
    int dd  = d & 63;
    int mod = dd < 16 ? 0 : (dd < 40 ? 1 : 2);
    size_t ci = (((size_t)mod * Bb + b) * Ss + s_) * HDv + d;
    float c = cosp[ci], sn = sinp[ci];
    float rh = (d < 64) ? -xs[d + 64] : xs[d - 64];
    float y = f2tf_f(xn * c + rh * sn);
    if (isq) g_qt[((size_t)(b * NH  + hh)        * Ss + s_) * HDv + d] = y;
    else     g_kt[((size_t)(b * NKV + (hh - NH)) * Ss + s_) * HDv + d] = y;
}

// ------------- flash attention with tf32 mma.sync --------------------------
#define FM  128
#define FNN 64
#define QS_OFF 0
#define KS_OFF 65536
#define KS_SZ  32768
#define VS_OFF 131072
#define VS_SZ  32768
#define PS_OFF 196608
#define FSMEM  229376

__global__ void __launch_bounds__(256, 1) flashmma_kernel()
{
    extern __shared__ float sm[];
    const uint32_t sb = smem_u32(sm);
    const int tid = threadIdx.x, lane = tid & 31, w = tid >> 5;
    const int qb = blockIdx.x, h = blockIdx.y, b = blockIdx.z;
    const int kv = h >> 1;

    const float* qbase = g_qt  + ((size_t)(b * NH  + h ) * Ss + qb * FM) * HDv;
    const float* kbase = g_kt  + ((size_t)(b * NKV + kv) * Ss) * HDv;
    const float* vbase = g_vtd + ((size_t)(b * NKV + kv) * HDv) * Ss;

    #pragma unroll
    for (int i = 0; i < 16; i++) {
        int idx = tid + i * 256;
        int row = idx >> 5, c = idx & 31;
        cp_async16(sb + QS_OFF + row * 512 + ((c ^ (row & 7)) * 16),
                   qbase + (size_t)row * HDv + c * 4);
    }
    cp_commit();

    auto loadKV = [&](int s, int kb) {
        uint32_t kB = sb + KS_OFF + s * KS_SZ;
        uint32_t vB = sb + VS_OFF + s * VS_SZ;
        #pragma unroll
        for (int i = 0; i < 8; i++) {
            int idx = tid + i * 256;
            int row = idx >> 5, c = idx & 31;
            cp_async16(kB + row * 512 + ((c ^ (row & 7)) * 16),
                       kbase + (size_t)(kb * FNN + row) * HDv + c * 4);
        }
        #pragma unroll
        for (int i = 0; i < 8; i++) {
            int idx = tid + i * 256;
            int row = idx >> 4, c = idx & 15;
            cp_async16(vB + row * 256 + ((c ^ (row & 7)) * 16),
                       vbase + (size_t)row * Ss + kb * FNN + c * 4);
        }
        cp_commit();
    };
    loadKV(0, 0);

    const int a_mat  = lane >> 3;
    const int a_rrow = (lane & 7) + ((a_mat & 1) << 3);
    const int a_crel = a_mat >> 1;
    const int b_rrow = lane & 7;
    const int b_mat  = lane >> 3;
    const int q0 = lane >> 2;
    const int c0 = (lane & 3) * 2;

    float o[16][4];
    #pragma unroll
    for (int nt = 0; nt < 16; nt++)
        #pragma unroll
        for (int q = 0; q < 4; q++) o[nt][q] = 0.f;
    float mrow[2] = {-1e30f, -1e30f}, lrow[2] = {0.f, 0.f};

    const int nkb = 2 * qb + 2;
    const int arow = w * 16 + a_rrow;

    for (int kb = 0; kb < nkb; kb++) {
        int s = kb & 1;
        cp_wait<0>();
        __syncthreads();
        if (kb + 1 < nkb) loadKV(s ^ 1, kb + 1);

        uint32_t kB = sb + KS_OFF + s * KS_SZ;
        uint32_t vB = sb + VS_OFF + s * VS_SZ;

        // ---- S = Q K^T ----
        float sfr[8][4];
        #pragma unroll
        for (int nt = 0; nt < 8; nt++)
            #pragma unroll
            for (int q = 0; q < 4; q++) sfr[nt][q] = 0.f;

        #pragma unroll
        for (int kp = 0; kp < 8; kp++) {
            uint32_t bfr[8][4];
            #pragma unroll
            for (int nt = 0; nt < 8; nt++) {
                int row = nt * 8 + b_rrow;
                int chunk = kp * 4 + b_mat;
                ldsm4(bfr[nt], kB + row * 512 + ((chunk ^ (row & 7)) * 16));
            }
            #pragma unroll
            for (int half = 0; half < 2; half++) {
                int ks = kp * 2 + half;
                uint32_t afr[4];
                int chunk = ks * 2 + a_crel;
                ldsm4(afr, sb + QS_OFF + arow * 512 + ((chunk ^ (arow & 7)) * 16));
                #pragma unroll
                for (int nt = 0; nt < 8; nt++)
                    mma1688(sfr[nt], afr, bfr[nt][half * 2], bfr[nt][half * 2 + 1]);
            }
        }

        // ---- online softmax ----
        const float scale = 0.08838834764831845f;
        const bool need_mask = (kb >= 2 * qb);
        #pragma unroll
        for (int r = 0; r < 2; r++) {
            int qi = qb * FM + w * 16 + q0 + r * 8;
            float vals[16];
            float mx = -1e30f;
            #pragma unroll
            for (int nt = 0; nt < 8; nt++)
                #pragma unroll
                for (int q = 0; q < 2; q++) {
                    float v = sfr[nt][r * 2 + q] * scale;
                    if (need_mask) {
                        int kj = kb * FNN + nt * 8 + c0 + q;
                        if (kj > qi) v = -1e30f;
                    }
                    vals[nt * 2 + q] = v;
                    mx = fmaxf(mx, v);
                }
            mx = fmaxf(mx, __shfl_xor_sync(0xffffffffu, mx, 1));
            mx = fmaxf(mx, __shfl_xor_sync(0xffffffffu, mx, 2));
            float mnew  = fmaxf(mrow[r], mx);
            float alpha = __expf(mrow[r] - mnew);
            float rs = 0.f;
            int prow = w * 16 + q0 + r * 8;
            #pragma unroll
            for (int nt = 0; nt < 8; nt++) {
                float p0 = __expf(vals[nt * 2]     - mnew);
                float p1 = __expf(vals[nt * 2 + 1] - mnew);
                rs += p0 + p1;
                int col = nt * 8 + c0;
                int chunk = col >> 2, within = col & 3;
                sts8(sb + PS_OFF + prow * 256 + ((chunk ^ (prow & 7)) * 16) + within * 4, p0, p1);
            }
            rs += __shfl_xor_sync(0xffffffffu, rs, 1);
            rs += __shfl_xor_sync(0xffffffffu, rs, 2);
            lrow[r] = lrow[r] * alpha + rs;
            mrow[r] = mnew;
            #pragma unroll
            for (int nt = 0; nt < 16; nt++) {
                o[nt][r * 2]     *= alpha;
                o[nt][r * 2 + 1] *= alpha;
            }
        }
        __syncwarp();

        // ---- P A-fragments (only cvt that remains) ----
        uint32_t pa[8][4];
        #pragma unroll
        for (int ks = 0; ks < 8; ks++) {
            int chunk = ks * 2 + a_crel;
            ldsm4(pa[ks], sb + PS_OFF + arow * 256 + ((chunk ^ (arow & 7)) * 16));
            #pragma unroll
            for (int q = 0; q < 4; q++) pa[ks][q] = f2tf(pa[ks][q]);
        }

        // ---- O += P V ----
        #pragma unroll
        for (int nt = 0; nt < 16; nt++) {
            #pragma unroll
            for (int kp = 0; kp < 4; kp++) {
                uint32_t bfr[4];
                int row = nt * 8 + b_rrow;
                int chunk = kp * 4 + b_mat;
                ldsm4(bfr, vB + row * 256 + ((chunk ^ (row & 7)) * 16));
                mma1688(o[nt], pa[kp * 2],     bfr[0], bfr[1]);
                mma1688(o[nt], pa[kp * 2 + 1], bfr[2], bfr[3]);
            }
        }
    }

    // epilogue (tf32-round for the O projection's A operand)
    #pragma unroll
    for (int r = 0; r < 2; r++) {
        float inv = 1.f / lrow[r];
        int row = qb * FM + w * 16 + q0 + r * 8;
        float* outp = g_attn + ((size_t)(b * Ss + row) * (NH * HDv)) + h * HDv;
        #pragma unroll
        for (int nt = 0; nt < 16; nt++)
            *(float2*)(outp + nt * 8 + c0) =
                make_float2(f2tf_f(o[nt][r * 2] * inv), f2tf_f(o[nt][r * 2 + 1] * inv));
    }
}

// --------------------------------- launch ---------------------------------
extern "C" void kernel_launch(void* const* d_in, const int* in_sizes, int n_in,
                              void* d_out, int out_size)
{
    const float* hs   = (const float*)d_in[0];
    const float* cosp = (const float*)d_in[1];
    const float* sinp = (const float*)d_in[2];
    // d_in[3] = attention_mask: exactly causal -1e9; implemented analytically
    const float* Wq = (const float*)d_in[4];
    const float* Wk = (const float*)d_in[5];
    const float* Wv = (const float*)d_in[6];
    const float* Wo = (const float*)d_in[7];
    const float* qw = (const float*)d_in[8];
    const float* kw = (const float*)d_in[9];
    float* out = (float*)d_out;

    void *phs, *pqkv, *pattn, *pwqkvt, *pwot;
    cudaGetSymbolAddress(&phs, g_hs_tf);
    cudaGetSymbolAddress(&pqkv, g_qkv);
    cudaGetSymbolAddress(&pattn, g_attn);
    cudaGetSymbolAddress(&pwqkvt, g_wqkvt);
    cudaGetSymbolAddress(&pwot, g_wot);

    // tf32-round activations
    cvt_kernel<<<(MS * Dd / 4 + 255) / 256, 256>>>(hs, (float*)phs, MS * Dd / 4);

    // packed weight transposes (+ tf32 round)
    dim3 tb(32, 8);
    transpose_kernel<<<dim3(Dd / 32, Dd / 32), tb>>>(Wq, (float*)pwqkvt, Dd, Dd);
    transpose_kernel<<<dim3(Dd / 32, (NKV * HDv) / 32), tb>>>(
        Wk, (float*)pwqkvt + (size_t)2048 * Dd, Dd, NKV * HDv);
    transpose_kernel<<<dim3(Dd / 32, (NKV * HDv) / 32), tb>>>(
        Wv, (float*)pwqkvt + (size_t)3072 * Dd, Dd, NKV * HDv);
    transpose_kernel<<<dim3(Dd / 32, Dd / 32), tb>>>(Wo, (float*)pwot, Dd, Dd);

    cudaFuncSetAttribute(mma_gemm_kernel,
                         cudaFuncAttributeMaxDynamicSharedMemorySize, GEMM_SMEM);
    // fused QKV projection: [4096, 2048] @ [2048, 4096]
    mma_gemm_kernel<<<dim3(NQKV / BN, MS / BM), 256, GEMM_SMEM>>>(
        (const float*)phs, (const float*)pwqkvt, (float*)pqkv, MS, NQKV, Dd);

    normrope_kernel<<<dim3(MS, NH + 2 * NKV), 128>>>(cosp, sinp, qw, kw);
    vtrans_kernel<<<dim3(Ss / 32, HDv / 32, Bb * NKV), tb>>>();

    cudaFuncSetAttribute(flashmma_kernel,
                         cudaFuncAttributeMaxDynamicSharedMemorySize, FSMEM);
    flashmma_kernel<<<dim3(Ss / FM, NH, Bb), 256, FSMEM>>>();

    mma_gemm_kernel<<<dim3(Dd / BN, MS / BM), 256, GEMM_SMEM>>>(
        (const float*)pattn, (const float*)pwot, out, MS, Dd, Dd);
}

// round 6
// speedup vs baseline: 7.0250x; 1.7726x over previous
#include <cuda_runtime.h>
#include <cuda_fp16.h>
#include <math.h>
#include <stdint.h>

#define Bb  2
#define Ss  2048
#define Dd  2048
#define HDv 128
#define NH  16
#define NKV 8
#define MS  (Bb*Ss)                 // 4096 tokens
#define NQKV (NH*HDv + 2*NKV*HDv)   // 4096

// ---------------- scratch (device globals; no allocation allowed) ----------
__device__ __half g_hs_h[MS*Dd];          // fp16 hidden states
__device__ float  g_qkv[MS*NQKV];         // fused QKV output (fp32 accum)
__device__ __half g_qt[Bb*NH*Ss*HDv];
__device__ __half g_kt[Bb*NKV*Ss*HDv];
__device__ __half g_vt[Bb*NKV*Ss*HDv];    // [b,kv,s,d]
__device__ __half g_vtd[Bb*NKV*HDv*Ss];   // [b,kv,d,s]
__device__ __half g_attn[MS*NH*HDv];      // fp16 (A operand of O-proj)
__device__ __half g_wqkvt[NQKV*Dd];       // packed [Wq^T;Wk^T;Wv^T] fp16
__device__ __half g_wot[Dd*Dd];           // Wo^T fp16

// ------------------------------ PTX helpers -------------------------------
__device__ __forceinline__ uint32_t smem_u32(const void* p) {
    uint32_t a;
    asm("{ .reg .u64 t; cvta.to.shared.u64 t, %1; cvt.u32.u64 %0, t; }" : "=r"(a) : "l"(p));
    return a;
}
__device__ __forceinline__ void cp_async16(uint32_t saddr, const void* g) {
    asm volatile("cp.async.cg.shared.global [%0], [%1], 16;" :: "r"(saddr), "l"(g));
}
__device__ __forceinline__ void cp_commit() { asm volatile("cp.async.commit_group;" ::: "memory"); }
template <int N> __device__ __forceinline__ void cp_wait() {
    asm volatile("cp.async.wait_group %0;" :: "n"(N) : "memory");
}
__device__ __forceinline__ void ldsm4(uint32_t* r, uint32_t addr) {
    asm volatile("ldmatrix.sync.aligned.m8n8.x4.shared.b16 {%0,%1,%2,%3}, [%4];"
                 : "=r"(r[0]), "=r"(r[1]), "=r"(r[2]), "=r"(r[3]) : "r"(addr));
}
__device__ __forceinline__ void sts_h2(uint32_t addr, float a, float b) {
    __half2 h = __floats2half2_rn(a, b);
    asm volatile("st.shared.u32 [%0], %1;" :: "r"(addr), "r"(*(uint32_t*)&h) : "memory");
}
__device__ __forceinline__ void mma_f16(float* d, const uint32_t* a, uint32_t b0, uint32_t b1) {
    asm volatile(
        "mma.sync.aligned.m16n8k16.row.col.f32.f16.f16.f32 "
        "{%0,%1,%2,%3}, {%4,%5,%6,%7}, {%8,%9}, {%0,%1,%2,%3};"
        : "+f"(d[0]), "+f"(d[1]), "+f"(d[2]), "+f"(d[3])
        : "r"(a[0]), "r"(a[1]), "r"(a[2]), "r"(a[3]), "r"(b0), "r"(b1));
}

// ---------- elementwise fp32 -> fp16 pass (for activations) ----------------
__global__ void cvt_half_kernel(const float* __restrict__ in, __half* __restrict__ out, int n4)
{
    int i = blockIdx.x * blockDim.x + threadIdx.x;
    if (i >= n4) return;
    float4 v = ((const float4*)in)[i];
    __half2 h0 = __floats2half2_rn(v.x, v.y);
    __half2 h1 = __floats2half2_rn(v.z, v.w);
    ((__half2*)out)[2 * i]     = h0;
    ((__half2*)out)[2 * i + 1] = h1;
}

// ----------- weight transpose + fp16: Wt[n,k] = h(W[k,n]) ------------------
__global__ void transpose_kernel(const float* __restrict__ W, __half* __restrict__ Wt,
                                 int K, int N)
{
    __shared__ float t[32][33];
    const int bx = blockIdx.x * 32;
    const int by = blockIdx.y * 32;
    const int tx = threadIdx.x, ty = threadIdx.y;
    #pragma unroll
    for (int i = 0; i < 32; i += 8)
        t[ty + i][tx] = W[(size_t)(bx + ty + i) * N + by + tx];
    __syncthreads();
    #pragma unroll
    for (int i = 0; i < 32; i += 8)
        Wt[(size_t)(by + ty + i) * K + bx + tx] = __float2half(t[tx][ty + i]);
}

// ------------- V transpose per head: [s, d] -> [d, s] ----------------------
__global__ void vtrans_kernel()
{
    __shared__ float t[32][33];
    const int bh = blockIdx.z;
    const int s0 = blockIdx.x * 32, d0 = blockIdx.y * 32;
    const int tx = threadIdx.x, ty = threadIdx.y;
    const __half* in = g_vt + (size_t)bh * Ss * HDv;
    __half* outp = g_vtd + (size_t)bh * HDv * Ss;
    #pragma unroll
    for (int i = 0; i < 32; i += 8)
        t[ty + i][tx] = __half2float(in[(size_t)(s0 + ty + i) * HDv + d0 + tx]);
    __syncthreads();
    #pragma unroll
    for (int i = 0; i < 32; i += 8)
        outp[(size_t)(d0 + ty + i) * Ss + s0 + tx] = __float2half(t[tx][ty + i]);
}

// --------- fp16 mma.sync GEMM: C[M,N] = A[M,K] @ Bt[N,K]^T -----------------
// K-chunk = 64 halves (128B rows), 3-stage cp.async, 8 warps of 64x32.
#define BM 128
#define BN 128
#define BKH 64                         // halves per chunk
#define NSTG 3
#define STG_BYTES (2 * BM * BKH * 2)   // A + B tile = 32 KB
#define GEMM_SMEM (NSTG * STG_BYTES)

__global__ void __launch_bounds__(256)
mma_gemm_kernel(const __half* __restrict__ A, const __half* __restrict__ Bt,
                float* __restrict__ C, int M, int N, int K)
{
    extern __shared__ float sm[];
    const int tid = threadIdx.x;
    const int lane = tid & 31, w = tid >> 5;
    const int wm = (w & 1) * 64;
    const int wn = (w >> 1) * 32;
    const int m0 = blockIdx.y * BM, n0 = blockIdx.x * BN;
    const __half* Ap = A  + (size_t)m0 * K;
    const __half* Bp = Bt + (size_t)n0 * K;
    const uint32_t sbase = smem_u32(sm);
    const int NCH = K / BKH;

    // ldmatrix lane geometry (A 16x16, B paired 2x(8x16))
    const int a_rrow = (lane & 7) + ((lane >> 3) & 1) * 8;
    const int a_crel = lane >> 4;                  // 16B chunk within k16
    const int b_rsub = ((lane >> 4) << 3) + (lane & 7);
    const int b_sel  = (lane >> 3) & 1;

    auto load_stage = [&](int s, int kt) {
        uint32_t aB = sbase + s * STG_BYTES;
        uint32_t bB = aB + BM * BKH * 2;
        int k0 = kt * BKH;
        #pragma unroll
        for (int i = 0; i < 4; i++) {
            int idx = tid + i * 256;
            int row = idx >> 3, c = idx & 7;       // 128 rows x 8 chunks
            uint32_t off = row * 128 + ((c ^ (row & 7)) * 16);
            cp_async16(aB + off, Ap + (size_t)row * K + k0 + c * 8);
            cp_async16(bB + off, Bp + (size_t)row * K + k0 + c * 8);
        }
        cp_commit();
    };

    #pragma unroll
    for (int s = 0; s < NSTG; s++) load_stage(s, s);

    float d[4][4][4];
    #pragma unroll
    for (int i = 0; i < 4; i++)
        #pragma unroll
        for (int j = 0; j < 4; j++)
            #pragma unroll
            for (int q = 0; q < 4; q++) d[i][j][q] = 0.f;

    for (int it = 0; it < NCH; it++) {
        cp_wait<NSTG - 1>();
        __syncthreads();
        uint32_t aB = sbase + (it % NSTG) * STG_BYTES;
        uint32_t bB = aB + BM * BKH * 2;

        #pragma unroll
        for (int ks = 0; ks < 4; ks++) {           // 4 k-steps of 16
            uint32_t afr[4][4];
            #pragma unroll
            for (int tm = 0; tm < 4; tm++) {
                int row = wm + tm * 16 + a_rrow;
                int chunk = ks * 2 + a_crel;
                ldsm4(afr[tm], aB + row * 128 + ((chunk ^ (row & 7)) * 16));
            }
            uint32_t bfr[2][4];                    // 2 pairs x (b0,b1,b0',b1')
            #pragma unroll
            for (int t = 0; t < 2; t++) {
                int row = wn + t * 16 + b_rsub;
                int chunk = ks * 2 + b_sel;
                ldsm4(bfr[t], bB + row * 128 + ((chunk ^ (row & 7)) * 16));
            }
            #pragma unroll
            for (int tm = 0; tm < 4; tm++)
                #pragma unroll
                for (int tn = 0; tn < 4; tn++)
                    mma_f16(d[tm][tn], afr[tm],
                            bfr[tn >> 1][(tn & 1) * 2], bfr[tn >> 1][(tn & 1) * 2 + 1]);
        }
        __syncthreads();
        if (it + NSTG < NCH) load_stage(it % NSTG, it + NSTG);
    }

    const int crow = lane >> 2, ccol = (lane & 3) * 2;
    #pragma unroll
    for (int tm = 0; tm < 4; tm++)
        #pragma unroll
        for (int tn = 0; tn < 4; tn++) {
            float* Cp = C + (size_t)(m0 + wm + tm * 16 + crow) * N + n0 + wn + tn * 8 + ccol;
            *(float2*)Cp                   = make_float2(d[tm][tn][0], d[tm][tn][1]);
            *(float2*)(Cp + 8 * (size_t)N) = make_float2(d[tm][tn][2], d[tm][tn][3]);
        }
}

// ------------- per-(token, head): RMSNorm + mRoPE + transpose -------------
__global__ void normrope_kernel(const float* __restrict__ cosp, const float* __restrict__ sinp,
                                const float* __restrict__ qw,   const float* __restrict__ kw)
{
    const int tok = blockIdx.x;
    const int hh  = blockIdx.y;
    const int d   = threadIdx.x;
    const int b = tok / Ss, s_ = tok % Ss;
    const float* row = g_qkv + (size_t)tok * NQKV;

    if (hh >= NH + NKV) {
        int h = hh - NH - NKV;
        g_vt[((size_t)(b * NKV + h) * Ss + s_) * HDv + d] =
            __float2half(row[3072 + h * HDv + d]);
        return;
    }
    __shared__ float xs[HDv];
    __shared__ float red[4];
    const bool isq = hh < NH;
    float x = isq ? row[hh * HDv + d] : row[2048 + (hh - NH) * HDv + d];
    float sq = x * x;
    #pragma unroll
    for (int off = 16; off > 0; off >>= 1) sq += __shfl_xor_sync(0xffffffffu, sq, off);
    if ((d & 31) == 0) red[d >> 5] = sq;
    __syncthreads();
    float var = (red[0] + red[1] + red[2] + red[3]) * (1.0f / HDv);
    float inv = rsqrtf(var + 1e-6f);
    float xn  = (isq ? qw[d] : kw[d]) * (x * inv);
    xs[d] = xn;
    __syncthreads();
    int dd  = d & 63;
    int mod = dd < 16 ? 0 : (dd < 40 ? 1 : 2);
    size_t ci = (((size_t)mod * Bb + b) * Ss + s_) * HDv + d;
    float c = cosp[ci], sn = sinp[ci];
    float rh = (d < 64) ? -xs[d + 64] : xs[d - 64];
    __half y = __float2half(xn * c + rh * sn);
    if (isq) g_qt[((size_t)(b * NH  + hh)        * Ss + s_) * HDv + d] = y;
    else     g_kt[((size_t)(b * NKV + (hh - NH)) * Ss + s_) * HDv + d] = y;
}

// ------------- flash attention with fp16 mma.sync --------------------------
#define FM  128
#define FNN 64
#define QS_OFF 0                 // 128 x 256B           (32 KB)
#define KS_OFF 32768             // 2 x (64 x 256B)      (32 KB)
#define KS_SZ  16384
#define VS_OFF 65536             // 2 x (128 x 128B)     (32 KB)
#define VS_SZ  16384
#define PS_OFF 98304             // 128 x 128B           (16 KB)
#define FSMEM  114688

__global__ void __launch_bounds__(256, 2) flashmma_kernel()
{
    extern __shared__ float sm[];
    const uint32_t sb = smem_u32(sm);
    const int tid = threadIdx.x, lane = tid & 31, w = tid >> 5;
    const int qb = gridDim.x - 1 - blockIdx.x;       // heavy tiles first
    const int h = blockIdx.y, b = blockIdx.z;
    const int kv = h >> 1;

    const __half* qbase = g_qt  + ((size_t)(b * NH  + h ) * Ss + qb * FM) * HDv;
    const __half* kbase = g_kt  + ((size_t)(b * NKV + kv) * Ss) * HDv;
    const __half* vbase = g_vtd + ((size_t)(b * NKV + kv) * HDv) * Ss;

    // Q tile: 128 rows x 16 chunks (256B rows)
    #pragma unroll
    for (int i = 0; i < 8; i++) {
        int idx = tid + i * 256;
        int row = idx >> 4, c = idx & 15;
        cp_async16(sb + QS_OFF + row * 256 + ((c ^ (row & 7)) * 16),
                   qbase + (size_t)row * HDv + c * 8);
    }
    cp_commit();

    auto loadKV = [&](int s, int kb) {
        uint32_t kB = sb + KS_OFF + s * KS_SZ;
        uint32_t vB = sb + VS_OFF + s * VS_SZ;
        #pragma unroll
        for (int i = 0; i < 4; i++) {
            int idx = tid + i * 256;
            int row = idx >> 4, c = idx & 15;        // 64 rows x 16 chunks
            cp_async16(kB + row * 256 + ((c ^ (row & 7)) * 16),
                       kbase + (size_t)(kb * FNN + row) * HDv + c * 8);
        }
        #pragma unroll
        for (int i = 0; i < 4; i++) {
            int idx = tid + i * 256;
            int row = idx >> 3, c = idx & 7;         // 128 rows x 8 chunks
            cp_async16(vB + row * 128 + ((c ^ (row & 7)) * 16),
                       vbase + (size_t)row * Ss + kb * FNN + c * 8);
        }
        cp_commit();
    };
    loadKV(0, 0);

    const int a_rrow = (lane & 7) + ((lane >> 3) & 1) * 8;
    const int a_crel = lane >> 4;
    const int b_rsub = ((lane >> 4) << 3) + (lane & 7);
    const int b_sel  = (lane >> 3) & 1;
    const int q0 = lane >> 2;
    const int c0 = (lane & 3) * 2;

    float o[16][4];
    #pragma unroll
    for (int nt = 0; nt < 16; nt++)
        #pragma unroll
        for (int q = 0; q < 4; q++) o[nt][q] = 0.f;
    float mrow[2] = {-1e30f, -1e30f}, lrow[2] = {0.f, 0.f};

    const int nkb = 2 * qb + 2;
    const int arow = w * 16 + a_rrow;

    for (int kb = 0; kb < nkb; kb++) {
        int s = kb & 1;
        cp_wait<0>();
        __syncthreads();
        if (kb + 1 < nkb) loadKV(s ^ 1, kb + 1);

        uint32_t kB = sb + KS_OFF + s * KS_SZ;
        uint32_t vB = sb + VS_OFF + s * VS_SZ;

        // ---- S = Q K^T : 16 q-rows x 64 keys per warp ----
        float sfr[8][4];
        #pragma unroll
        for (int nt = 0; nt < 8; nt++)
            #pragma unroll
            for (int q = 0; q < 4; q++) sfr[nt][q] = 0.f;

        #pragma unroll
        for (int ks = 0; ks < 8; ks++) {             // d = 8 x k16
            uint32_t afr[4];
            {
                int chunk = ks * 2 + a_crel;
                ldsm4(afr, sb + QS_OFF + arow * 256 + ((chunk ^ (arow & 7)) * 16));
            }
            uint32_t bfr[4][4];                      // 4 pairs -> 8 key-tiles
            #pragma unroll
            for (int t = 0; t < 4; t++) {
                int row = t * 16 + b_rsub;
                int chunk = ks * 2 + b_sel;
                ldsm4(bfr[t], kB + row * 256 + ((chunk ^ (row & 7)) * 16));
            }
            #pragma unroll
            for (int nt = 0; nt < 8; nt++)
                mma_f16(sfr[nt], afr,
                        bfr[nt >> 1][(nt & 1) * 2], bfr[nt >> 1][(nt & 1) * 2 + 1]);
        }

        // ---- online softmax ----
        const float scale = 0.08838834764831845f;
        const bool need_mask = (kb >= 2 * qb);
        #pragma unroll
        for (int r = 0; r < 2; r++) {
            int qi = qb * FM + w * 16 + q0 + r * 8;
            float vals[16];
            float mx = -1e30f;
            #pragma unroll
            for (int nt = 0; nt < 8; nt++)
                #pragma unroll
                for (int q = 0; q < 2; q++) {
                    float v = sfr[nt][r * 2 + q] * scale;
                    if (need_mask) {
                        int kj = kb * FNN + nt * 8 + c0 + q;
                        if (kj > qi) v = -1e30f;
                    }
                    vals[nt * 2 + q] = v;
                    mx = fmaxf(mx, v);
                }
            mx = fmaxf(mx, __shfl_xor_sync(0xffffffffu, mx, 1));
            mx = fmaxf(mx, __shfl_xor_sync(0xffffffffu, mx, 2));
            float mnew  = fmaxf(mrow[r], mx);
            float alpha = __expf(mrow[r] - mnew);
            float rs = 0.f;
            int prow = w * 16 + q0 + r * 8;
            #pragma unroll
            for (int nt = 0; nt < 8; nt++) {
                float p0 = __expf(vals[nt * 2]     - mnew);
                float p1 = __expf(vals[nt * 2 + 1] - mnew);
                rs += p0 + p1;
                // P row = 64 halves = 8 chunks; col = nt*8 + c0 -> chunk nt
                sts_h2(sb + PS_OFF + prow * 128 + ((nt ^ (prow & 7)) * 16) + c0 * 2, p0, p1);
            }
            rs += __shfl_xor_sync(0xffffffffu, rs, 1);
            rs += __shfl_xor_sync(0xffffffffu, rs, 2);
            lrow[r] = lrow[r] * alpha + rs;
            mrow[r] = mnew;
            #pragma unroll
            for (int nt = 0; nt < 16; nt++) {
                o[nt][r * 2]     *= alpha;
                o[nt][r * 2 + 1] *= alpha;
            }
        }
        __syncwarp();

        // ---- P A-fragments (warp-local rows, fp16 already) ----
        uint32_t pa[4][4];
        #pragma unroll
        for (int ks = 0; ks < 4; ks++) {             // keys = 4 x k16
            int chunk = ks * 2 + a_crel;
            ldsm4(pa[ks], sb + PS_OFF + arow * 128 + ((chunk ^ (arow & 7)) * 16));
        }

        // ---- O += P V ----
        #pragma unroll
        for (int ks = 0; ks < 4; ks++) {
            uint32_t bfr[8][4];                      // 8 pairs -> 16 d-tiles
            #pragma unroll
            for (int t = 0; t < 8; t++) {
                int row = t * 16 + b_rsub;
                int chunk = ks * 2 + b_sel;
                ldsm4(bfr[t], vB + row * 128 + ((chunk ^ (row & 7)) * 16));
            }
            #pragma unroll
            for (int nt = 0; nt < 16; nt++)
                mma_f16(o[nt], pa[ks],
                        bfr[nt >> 1][(nt & 1) * 2], bfr[nt >> 1][(nt & 1) * 2 + 1]);
        }
    }

    // epilogue: fp16 out (A operand of O projection)
    #pragma unroll
    for (int r = 0; r < 2; r++) {
        float inv = 1.f / lrow[r];
        int row = qb * FM + w * 16 + q0 + r * 8;
        __half* outp = g_attn + ((size_t)(b * Ss + row) * (NH * HDv)) + h * HDv;
        #pragma unroll
        for (int nt = 0; nt < 16; nt++) {
            __half2 hv = __floats2half2_rn(o[nt][r * 2] * inv, o[nt][r * 2 + 1] * inv);
            *(__half2*)(outp + nt * 8 + c0) = hv;
        }
    }
}

// --------------------------------- launch ---------------------------------
extern "C" void kernel_launch(void* const* d_in, const int* in_sizes, int n_in,
                              void* d_out, int out_size)
{
    const float* hs   = (const float*)d_in[0];
    const float* cosp = (const float*)d_in[1];
    const float* sinp = (const float*)d_in[2];
    // d_in[3] = attention_mask: exactly causal -1e9; implemented analytically
    const float* Wq = (const float*)d_in[4];
    const float* Wk = (const float*)d_in[5];
    const float* Wv = (const float*)d_in[6];
    const float* Wo = (const float*)d_in[7];
    const float* qw = (const float*)d_in[8];
    const float* kw = (const float*)d_in[9];
    float* out = (float*)d_out;

    void *phs, *pqkv, *pattn, *pwqkvt, *pwot;
    cudaGetSymbolAddress(&phs, g_hs_h);
    cudaGetSymbolAddress(&pqkv, g_qkv);
    cudaGetSymbolAddress(&pattn, g_attn);
    cudaGetSymbolAddress(&pwqkvt, g_wqkvt);
    cudaGetSymbolAddress(&pwot, g_wot);

    cvt_half_kernel<<<(MS * Dd / 4 + 255) / 256, 256>>>(hs, (__half*)phs, MS * Dd / 4);

    dim3 tb(32, 8);
    transpose_kernel<<<dim3(Dd / 32, Dd / 32), tb>>>(Wq, (__half*)pwqkvt, Dd, Dd);
    transpose_kernel<<<dim3(Dd / 32, (NKV * HDv) / 32), tb>>>(
        Wk, (__half*)pwqkvt + (size_t)2048 * Dd, Dd, NKV * HDv);
    transpose_kernel<<<dim3(Dd / 32, (NKV * HDv) / 32), tb>>>(
        Wv, (__half*)pwqkvt + (size_t)3072 * Dd, Dd, NKV * HDv);
    transpose_kernel<<<dim3(Dd / 32, Dd / 32), tb>>>(Wo, (__half*)pwot, Dd, Dd);

    cudaFuncSetAttribute(mma_gemm_kernel,
                         cudaFuncAttributeMaxDynamicSharedMemorySize, GEMM_SMEM);
    // fused QKV projection
    mma_gemm_kernel<<<dim3(NQKV / BN, MS / BM), 256, GEMM_SMEM>>>(
        (const __half*)phs, (const __half*)pwqkvt, (float*)pqkv, MS, NQKV, Dd);

    normrope_kernel<<<dim3(MS, NH + 2 * NKV), 128>>>(cosp, sinp, qw, kw);
    vtrans_kernel<<<dim3(Ss / 32, HDv / 32, Bb * NKV), tb>>>();

    cudaFuncSetAttribute(flashmma_kernel,
                         cudaFuncAttributeMaxDynamicSharedMemorySize, FSMEM);
    flashmma_kernel<<<dim3(Ss / FM, NH, Bb), 256, FSMEM>>>();

    mma_gemm_kernel<<<dim3(Dd / BN, MS / BM), 256, GEMM_SMEM>>>(
        (const __half*)pattn, (const __half*)pwot, out, MS, Dd, Dd);
}

// round 7
// speedup vs baseline: 7.7560x; 1.1041x over previous
#include <cuda_runtime.h>
#include <cuda_fp16.h>
#include <math.h>
#include <stdint.h>

#define Bb  2
#define Ss  2048
#define Dd  2048
#define HDv 128
#define NH  16
#define NKV 8
#define MS  (Bb*Ss)                 // 4096 tokens
#define NQKV (NH*HDv + 2*NKV*HDv)   // 4096

// ---------------- scratch (device globals; no allocation allowed) ----------
__device__ __half g_hs_h[MS*Dd];          // fp16 hidden states
__device__ float  g_qkv[MS*NQKV];         // fused QKV output (fp32 accum)
__device__ __half g_qt[Bb*NH*Ss*HDv];
__device__ __half g_kt[Bb*NKV*Ss*HDv];
__device__ __half g_vtd[Bb*NKV*HDv*Ss];   // [b,kv,d,s]
__device__ __half g_attn[MS*NH*HDv];      // fp16 (A operand of O-proj)
__device__ __half g_wqkvt[NQKV*Dd];       // packed [Wq^T;Wk^T;Wv^T] fp16
__device__ __half g_wot[Dd*Dd];           // Wo^T fp16

// ------------------------------ PTX helpers -------------------------------
__device__ __forceinline__ uint32_t smem_u32(const void* p) {
    uint32_t a;
    asm("{ .reg .u64 t; cvta.to.shared.u64 t, %1; cvt.u32.u64 %0, t; }" : "=r"(a) : "l"(p));
    return a;
}
__device__ __forceinline__ void cp_async16(uint32_t saddr, const void* g) {
    asm volatile("cp.async.cg.shared.global [%0], [%1], 16;" :: "r"(saddr), "l"(g));
}
__device__ __forceinline__ void cp_commit() { asm volatile("cp.async.commit_group;" ::: "memory"); }
template <int N> __device__ __forceinline__ void cp_wait() {
    asm volatile("cp.async.wait_group %0;" :: "n"(N) : "memory");
}
__device__ __forceinline__ void ldsm4(uint32_t* r, uint32_t addr) {
    asm volatile("ldmatrix.sync.aligned.m8n8.x4.shared.b16 {%0,%1,%2,%3}, [%4];"
                 : "=r"(r[0]), "=r"(r[1]), "=r"(r[2]), "=r"(r[3]) : "r"(addr));
}
__device__ __forceinline__ void sts_h2(uint32_t addr, float a, float b) {
    __half2 h = __floats2half2_rn(a, b);
    asm volatile("st.shared.u32 [%0], %1;" :: "r"(addr), "r"(*(uint32_t*)&h) : "memory");
}
__device__ __forceinline__ void mma_f16(float* d, const uint32_t* a, uint32_t b0, uint32_t b1) {
    asm volatile(
        "mma.sync.aligned.m16n8k16.row.col.f32.f16.f16.f32 "
        "{%0,%1,%2,%3}, {%4,%5,%6,%7}, {%8,%9}, {%0,%1,%2,%3};"
        : "+f"(d[0]), "+f"(d[1]), "+f"(d[2]), "+f"(d[3])
        : "r"(a[0]), "r"(a[1]), "r"(a[2]), "r"(a[3]), "r"(b0), "r"(b1));
}

// ---------- elementwise fp32 -> fp16 pass (for activations) ----------------
__global__ void cvt_half_kernel(const float* __restrict__ in, __half* __restrict__ out, int n4)
{
    int i = blockIdx.x * blockDim.x + threadIdx.x;
    if (i >= n4) return;
    float4 v = ((const float4*)in)[i];
    ((__half2*)out)[2 * i]     = __floats2half2_rn(v.x, v.y);
    ((__half2*)out)[2 * i + 1] = __floats2half2_rn(v.z, v.w);
}

// ----------- merged weight transpose + fp16: all 4 matrices, z-indexed -----
__global__ void transpose_all_kernel(const float* __restrict__ Wq, const float* __restrict__ Wk,
                                     const float* __restrict__ Wv, const float* __restrict__ Wo)
{
    __shared__ float t[32][33];
    const int z = blockIdx.z;
    const float* W; __half* Wt; int N;
    if      (z == 0) { W = Wq; Wt = g_wqkvt;                      N = 2048; }
    else if (z == 1) { W = Wk; Wt = g_wqkvt + (size_t)2048 * Dd;  N = 1024; }
    else if (z == 2) { W = Wv; Wt = g_wqkvt + (size_t)3072 * Dd;  N = 1024; }
    else             { W = Wo; Wt = g_wot;                        N = 2048; }
    const int by = blockIdx.y * 32;         // n block
    if (by >= N) return;
    const int bx = blockIdx.x * 32;         // k block
    const int tx = threadIdx.x, ty = threadIdx.y;
    #pragma unroll
    for (int i = 0; i < 32; i += 8)
        t[ty + i][tx] = W[(size_t)(bx + ty + i) * N + by + tx];
    __syncthreads();
    #pragma unroll
    for (int i = 0; i < 32; i += 8)
        Wt[(size_t)(by + ty + i) * Dd + bx + tx] = __float2half(t[tx][ty + i]);
}

// ------------- V transpose from g_qkv: [tok, d] -> [b,kv,d,s] fp16 ---------
__global__ void vtrans_kernel()
{
    __shared__ float t[32][33];
    const int bh = blockIdx.z;              // b*NKV + kv
    const int b = bh / NKV, kvh = bh % NKV;
    const int s0 = blockIdx.x * 32, d0 = blockIdx.y * 32;
    const int tx = threadIdx.x, ty = threadIdx.y;
    const float* in = g_qkv + (size_t)(b * Ss) * NQKV + 3072 + kvh * HDv;
    __half* outp = g_vtd + (size_t)bh * HDv * Ss;
    #pragma unroll
    for (int i = 0; i < 32; i += 8)
        t[ty + i][tx] = in[(size_t)(s0 + ty + i) * NQKV + d0 + tx];
    __syncthreads();
    #pragma unroll
    for (int i = 0; i < 32; i += 8)
        outp[(size_t)(d0 + ty + i) * Ss + s0 + tx] = __float2half(t[tx][ty + i]);
}

// --------- fp16 mma.sync GEMM: C[M,N] = A[M,K] @ Bt[N,K]^T -----------------
#define BM 128
#define BN 128
#define BKH 64
#define NSTG 3
#define STG_BYTES (2 * BM * BKH * 2)
#define GEMM_SMEM (NSTG * STG_BYTES)

__global__ void __launch_bounds__(256)
mma_gemm_kernel(const __half* __restrict__ A, const __half* __restrict__ Bt,
                float* __restrict__ C, int M, int N, int K)
{
    extern __shared__ float sm[];
    const int tid = threadIdx.x;
    const int lane = tid & 31, w = tid >> 5;
    const int wm = (w & 1) * 64;
    const int wn = (w >> 1) * 32;
    const int m0 = blockIdx.y * BM, n0 = blockIdx.x * BN;
    const __half* Ap = A  + (size_t)m0 * K;
    const __half* Bp = Bt + (size_t)n0 * K;
    const uint32_t sbase = smem_u32(sm);
    const int NCH = K / BKH;

    const int a_rrow = (lane & 7) + ((lane >> 3) & 1) * 8;
    const int a_crel = lane >> 4;
    const int b_rsub = ((lane >> 4) << 3) + (lane & 7);
    const int b_sel  = (lane >> 3) & 1;

    auto load_stage = [&](int s, int kt) {
        uint32_t aB = sbase + s * STG_BYTES;
        uint32_t bB = aB + BM * BKH * 2;
        int k0 = kt * BKH;
        #pragma unroll
        for (int i = 0; i < 4; i++) {
            int idx = tid + i * 256;
            int row = idx >> 3, c = idx & 7;
            uint32_t off = row * 128 + ((c ^ (row & 7)) * 16);
            cp_async16(aB + off, Ap + (size_t)row * K + k0 + c * 8);
            cp_async16(bB + off, Bp + (size_t)row * K + k0 + c * 8);
        }
        cp_commit();
    };

    #pragma unroll
    for (int s = 0; s < NSTG; s++) load_stage(s, s);

    float d[4][4][4];
    #pragma unroll
    for (int i = 0; i < 4; i++)
        #pragma unroll
        for (int j = 0; j < 4; j++)
            #pragma unroll
            for (int q = 0; q < 4; q++) d[i][j][q] = 0.f;

    for (int it = 0; it < NCH; it++) {
        cp_wait<NSTG - 1>();
        __syncthreads();
        uint32_t aB = sbase + (it % NSTG) * STG_BYTES;
        uint32_t bB = aB + BM * BKH * 2;

        #pragma unroll
        for (int ks = 0; ks < 4; ks++) {
            uint32_t afr[4][4];
            #pragma unroll
            for (int tm = 0; tm < 4; tm++) {
                int row = wm + tm * 16 + a_rrow;
                int chunk = ks * 2 + a_crel;
                ldsm4(afr[tm], aB + row * 128 + ((chunk ^ (row & 7)) * 16));
            }
            uint32_t bfr[2][4];
            #pragma unroll
            for (int t = 0; t < 2; t++) {
                int row = wn + t * 16 + b_rsub;
                int chunk = ks * 2 + b_sel;
                ldsm4(bfr[t], bB + row * 128 + ((chunk ^ (row & 7)) * 16));
            }
            #pragma unroll
            for (int tm = 0; tm < 4; tm++)
                #pragma unroll
                for (int tn = 0; tn < 4; tn++)
                    mma_f16(d[tm][tn], afr[tm],
                            bfr[tn >> 1][(tn & 1) * 2], bfr[tn >> 1][(tn & 1) * 2 + 1]);
        }
        __syncthreads();
        if (it + NSTG < NCH) load_stage(it % NSTG, it + NSTG);
    }

    const int crow = lane >> 2, ccol = (lane & 3) * 2;
    #pragma unroll
    for (int tm = 0; tm < 4; tm++)
        #pragma unroll
        for (int tn = 0; tn < 4; tn++) {
            float* Cp = C + (size_t)(m0 + wm + tm * 16 + crow) * N + n0 + wn + tn * 8 + ccol;
            *(float2*)Cp                   = make_float2(d[tm][tn][0], d[tm][tn][1]);
            *(float2*)(Cp + 8 * (size_t)N) = make_float2(d[tm][tn][2], d[tm][tn][3]);
        }
}

// ------------- normrope v2: warp-per-head, shfl-only ----------------------
// block = 256 thr (8 warps) per token; each warp does 3 of the 24 norm heads.
__global__ void __launch_bounds__(256) normrope_kernel(
    const float* __restrict__ cosp, const float* __restrict__ sinp,
    const float* __restrict__ qw,   const float* __restrict__ kw)
{
    const int tok = blockIdx.x;
    const int lane = threadIdx.x & 31, warp = threadIdx.x >> 5;
    const int b = tok / Ss, s_ = tok % Ss;
    const float* row = g_qkv + (size_t)tok * NQKV;

    const int d0 = lane * 4;
    const int dd = d0 & 63;
    const int mod = dd < 16 ? 0 : (dd < 40 ? 1 : 2);
    const size_t ci = (((size_t)mod * Bb + b) * Ss + s_) * HDv + d0;
    const float4 c4 = *(const float4*)(cosp + ci);
    const float4 s4 = *(const float4*)(sinp + ci);
    const float sgn = (lane < 16) ? -1.f : 1.f;

    #pragma unroll
    for (int t3 = 0; t3 < 3; t3++) {
        const int t = warp + t3 * 8;          // 0..23
        const bool isq = t < 16;
        const float* src = isq ? row + t * HDv : row + 2048 + (t - 16) * HDv;
        float4 x = *(const float4*)(src + d0);
        float sq = x.x * x.x + x.y * x.y + x.z * x.z + x.w * x.w;
        #pragma unroll
        for (int off = 16; off > 0; off >>= 1) sq += __shfl_xor_sync(0xffffffffu, sq, off);
        const float inv = rsqrtf(sq * (1.0f / HDv) + 1e-6f);
        const float4 w4 = *(const float4*)((isq ? qw : kw) + d0);
        float4 xn;
        xn.x = w4.x * (x.x * inv); xn.y = w4.y * (x.y * inv);
        xn.z = w4.z * (x.z * inv); xn.w = w4.w * (x.w * inv);
        // rotate_half partner: lane ^ 16, same sub-index
        float4 p;
        p.x = sgn * __shfl_xor_sync(0xffffffffu, xn.x, 16);
        p.y = sgn * __shfl_xor_sync(0xffffffffu, xn.y, 16);
        p.z = sgn * __shfl_xor_sync(0xffffffffu, xn.z, 16);
        p.w = sgn * __shfl_xor_sync(0xffffffffu, xn.w, 16);
        __half2 y0 = __floats2half2_rn(xn.x * c4.x + p.x * s4.x, xn.y * c4.y + p.y * s4.y);
        __half2 y1 = __floats2half2_rn(xn.z * c4.z + p.z * s4.z, xn.w * c4.w + p.w * s4.w);
        __half* dst = isq
            ? g_qt + ((size_t)(b * NH  + t)        * Ss + s_) * HDv + d0
            : g_kt + ((size_t)(b * NKV + (t - 16)) * Ss + s_) * HDv + d0;
        *(__half2*)dst       = y0;
        *(__half2*)(dst + 2) = y1;
    }
}

// ------------- flash attention with fp16 mma.sync --------------------------
#define FM  128
#define FNN 64
#define QS_OFF 0
#define KS_OFF 32768
#define KS_SZ  16384
#define VS_OFF 65536
#define VS_SZ  16384
#define PS_OFF 98304
#define FSMEM  114688

__global__ void __launch_bounds__(256, 2) flashmma_kernel()
{
    extern __shared__ float sm[];
    const uint32_t sb = smem_u32(sm);
    const int tid = threadIdx.x, lane = tid & 31, w = tid >> 5;
    const int qb = gridDim.x - 1 - blockIdx.x;
    const int h = blockIdx.y, b = blockIdx.z;
    const int kv = h >> 1;

    const __half* qbase = g_qt  + ((size_t)(b * NH  + h ) * Ss + qb * FM) * HDv;
    const __half* kbase = g_kt  + ((size_t)(b * NKV + kv) * Ss) * HDv;
    const __half* vbase = g_vtd + ((size_t)(b * NKV + kv) * HDv) * Ss;

    #pragma unroll
    for (int i = 0; i < 8; i++) {
        int idx = tid + i * 256;
        int row = idx >> 4, c = idx & 15;
        cp_async16(sb + QS_OFF + row * 256 + ((c ^ (row & 7)) * 16),
                   qbase + (size_t)row * HDv + c * 8);
    }
    cp_commit();

    auto loadKV = [&](int s, int kb) {
        uint32_t kB = sb + KS_OFF + s * KS_SZ;
        uint32_t vB = sb + VS_OFF + s * VS_SZ;
        #pragma unroll
        for (int i = 0; i < 4; i++) {
            int idx = tid + i * 256;
            int row = idx >> 4, c = idx & 15;
            cp_async16(kB + row * 256 + ((c ^ (row & 7)) * 16),
                       kbase + (size_t)(kb * FNN + row) * HDv + c * 8);
        }
        #pragma unroll
        for (int i = 0; i < 4; i++) {
            int idx = tid + i * 256;
            int row = idx >> 3, c = idx & 7;
            cp_async16(vB + row * 128 + ((c ^ (row & 7)) * 16),
                       vbase + (size_t)row * Ss + kb * FNN + c * 8);
        }
        cp_commit();
    };
    loadKV(0, 0);

    const int a_rrow = (lane & 7) + ((lane >> 3) & 1) * 8;
    const int a_crel = lane >> 4;
    const int b_rsub = ((lane >> 4) << 3) + (lane & 7);
    const int b_sel  = (lane >> 3) & 1;
    const int q0 = lane >> 2;
    const int c0 = (lane & 3) * 2;

    float o[16][4];
    #pragma unroll
    for (int nt = 0; nt < 16; nt++)
        #pragma unroll
        for (int q = 0; q < 4; q++) o[nt][q] = 0.f;
    float mrow[2] = {-1e30f, -1e30f}, lrow[2] = {0.f, 0.f};

    const int nkb = 2 * qb + 2;
    const int arow = w * 16 + a_rrow;

    for (int kb = 0; kb < nkb; kb++) {
        int s = kb & 1;
        cp_wait<0>();
        __syncthreads();
        if (kb + 1 < nkb) loadKV(s ^ 1, kb + 1);

        uint32_t kB = sb + KS_OFF + s * KS_SZ;
        uint32_t vB = sb + VS_OFF + s * VS_SZ;

        float sfr[8][4];
        #pragma unroll
        for (int nt = 0; nt < 8; nt++)
            #pragma unroll
            for (int q = 0; q < 4; q++) sfr[nt][q] = 0.f;

        #pragma unroll
        for (int ks = 0; ks < 8; ks++) {
            uint32_t afr[4];
            {
                int chunk = ks * 2 + a_crel;
                ldsm4(afr, sb + QS_OFF + arow * 256 + ((chunk ^ (arow & 7)) * 16));
            }
            uint32_t bfr[4][4];
            #pragma unroll
            for (int t = 0; t < 4; t++) {
                int row = t * 16 + b_rsub;
                int chunk = ks * 2 + b_sel;
                ldsm4(bfr[t], kB + row * 256 + ((chunk ^ (row & 7)) * 16));
            }
            #pragma unroll
            for (int nt = 0; nt < 8; nt++)
                mma_f16(sfr[nt], afr,
                        bfr[nt >> 1][(nt & 1) * 2], bfr[nt >> 1][(nt & 1) * 2 + 1]);
        }

        const float scale = 0.08838834764831845f;
        const bool need_mask = (kb >= 2 * qb);
        #pragma unroll
        for (int r = 0; r < 2; r++) {
            int qi = qb * FM + w * 16 + q0 + r * 8;
            float vals[16];
            float mx = -1e30f;
            #pragma unroll
            for (int nt = 0; nt < 8; nt++)
                #pragma unroll
                for (int q = 0; q < 2; q++) {
                    float v = sfr[nt][r * 2 + q] * scale;
                    if (need_mask) {
                        int kj = kb * FNN + nt * 8 + c0 + q;
                        if (kj > qi) v = -1e30f;
                    }
                    vals[nt * 2 + q] = v;
                    mx = fmaxf(mx, v);
                }
            mx = fmaxf(mx, __shfl_xor_sync(0xffffffffu, mx, 1));
            mx = fmaxf(mx, __shfl_xor_sync(0xffffffffu, mx, 2));
            float mnew  = fmaxf(mrow[r], mx);
            float alpha = __expf(mrow[r] - mnew);
            float rs = 0.f;
            int prow = w * 16 + q0 + r * 8;
            #pragma unroll
            for (int nt = 0; nt < 8; nt++) {
                float p0 = __expf(vals[nt * 2]     - mnew);
                float p1 = __expf(vals[nt * 2 + 1] - mnew);
                rs += p0 + p1;
                sts_h2(sb + PS_OFF + prow * 128 + ((nt ^ (prow & 7)) * 16) + c0 * 2, p0, p1);
            }
            rs += __shfl_xor_sync(0xffffffffu, rs, 1);
            rs += __shfl_xor_sync(0xffffffffu, rs, 2);
            lrow[r] = lrow[r] * alpha + rs;
            mrow[r] = mnew;
            #pragma unroll
            for (int nt = 0; nt < 16; nt++) {
                o[nt][r * 2]     *= alpha;
                o[nt][r * 2 + 1] *= alpha;
            }
        }
        __syncwarp();

        uint32_t pa[4][4];
        #pragma unroll
        for (int ks = 0; ks < 4; ks++) {
            int chunk = ks * 2 + a_crel;
            ldsm4(pa[ks], sb + PS_OFF + arow * 128 + ((chunk ^ (arow & 7)) * 16));
        }

        #pragma unroll
        for (int ks = 0; ks < 4; ks++) {
            uint32_t bfr[8][4];
            #pragma unroll
            for (int t = 0; t < 8; t++) {
                int row = t * 16 + b_rsub;
                int chunk = ks * 2 + b_sel;
                ldsm4(bfr[t], vB + row * 128 + ((chunk ^ (row & 7)) * 16));
            }
            #pragma unroll
            for (int nt = 0; nt < 16; nt++)
                mma_f16(o[nt], pa[ks],
                        bfr[nt >> 1][(nt & 1) * 2], bfr[nt >> 1][(nt & 1) * 2 + 1]);
        }
    }

    #pragma unroll
    for (int r = 0; r < 2; r++) {
        float inv = 1.f / lrow[r];
        int row = qb * FM + w * 16 + q0 + r * 8;
        __half* outp = g_attn + ((size_t)(b * Ss + row) * (NH * HDv)) + h * HDv;
        #pragma unroll
        for (int nt = 0; nt < 16; nt++) {
            __half2 hv = __floats2half2_rn(o[nt][r * 2] * inv, o[nt][r * 2 + 1] * inv);
            *(__half2*)(outp + nt * 8 + c0) = hv;
        }
    }
}

// --------------------------------- launch ---------------------------------
extern "C" void kernel_launch(void* const* d_in, const int* in_sizes, int n_in,
                              void* d_out, int out_size)
{
    const float* hs   = (const float*)d_in[0];
    const float* cosp = (const float*)d_in[1];
    const float* sinp = (const float*)d_in[2];
    // d_in[3] = attention_mask: exactly causal -1e9; implemented analytically
    const float* Wq = (const float*)d_in[4];
    const float* Wk = (const float*)d_in[5];
    const float* Wv = (const float*)d_in[6];
    const float* Wo = (const float*)d_in[7];
    const float* qw = (const float*)d_in[8];
    const float* kw = (const float*)d_in[9];
    float* out = (float*)d_out;

    void *phs, *pqkv, *pattn, *pwqkvt, *pwot;
    cudaGetSymbolAddress(&phs, g_hs_h);
    cudaGetSymbolAddress(&pqkv, g_qkv);
    cudaGetSymbolAddress(&pattn, g_attn);
    cudaGetSymbolAddress(&pwqkvt, g_wqkvt);
    cudaGetSymbolAddress(&pwot, g_wot);

    cvt_half_kernel<<<(MS * Dd / 4 + 255) / 256, 256>>>(hs, (__half*)phs, MS * Dd / 4);

    dim3 tb(32, 8);
    transpose_all_kernel<<<dim3(Dd / 32, Dd / 32, 4), tb>>>(Wq, Wk, Wv, Wo);

    cudaFuncSetAttribute(mma_gemm_kernel,
                         cudaFuncAttributeMaxDynamicSharedMemorySize, GEMM_SMEM);
    mma_gemm_kernel<<<dim3(NQKV / BN, MS / BM), 256, GEMM_SMEM>>>(
        (const __half*)phs, (const __half*)pwqkvt, (float*)pqkv, MS, NQKV, Dd);

    normrope_kernel<<<MS, 256>>>(cosp, sinp, qw, kw);
    vtrans_kernel<<<dim3(Ss / 32, HDv / 32, Bb * NKV), tb>>>();

    cudaFuncSetAttribute(flashmma_kernel,
                         cudaFuncAttributeMaxDynamicSharedMemorySize, FSMEM);
    flashmma_kernel<<<dim3(Ss / FM, NH, Bb), 256, FSMEM>>>();

    mma_gemm_kernel<<<dim3(Dd / BN, MS / BM), 256, GEMM_SMEM>>>(
        (const __half*)pattn, (const __half*)pwot, out, MS, Dd, Dd);
}